// round 12
// baseline (speedup 1.0000x reference)
#include <cuda_runtime.h>
#include <math.h>

#define NN 50000
#define EE 800000
#define HIDN 128
#define GG 64
#define TROW 132   // T row: 128 (T[h][c]) + 4 (B[h])

// ---------------- scratch (static device globals; no runtime allocation) ----------------
__device__ float d_q[NN * HIDN];
__device__ float d_k[NN * HIDN];
__device__ float d_v[NN * HIDN];
__device__ float d_T[NN * TROW];
__device__ float d_tmp[NN * HIDN];
__device__ float d_agg[NN * HIDN];
__device__ float d_eaP[EE * 32];
__device__ int   d_deg[NN];
__device__ int   d_cnt2[NN];
__device__ int   d_off[NN + 1];
__device__ int   d_srcPerm[EE];
__device__ int   d_posOf[EE];
__device__ float d_gsum[GG * HIDN];
__device__ unsigned d_gmaxk[GG * HIDN];
__device__ int   d_gcnt[GG];

static __device__ __forceinline__ float4 ld4(const float* p) { return *reinterpret_cast<const float4*>(p); }
static __device__ __forceinline__ float4 ld4g(const float* p) { return __ldg(reinterpret_cast<const float4*>(p)); }
static __device__ __forceinline__ void st4(float* p, float4 v) { *reinterpret_cast<float4*>(p) = v; }

static __device__ __forceinline__ unsigned enc_f(float f) {
    unsigned b = __float_as_uint(f);
    return (b & 0x80000000u) ? ~b : (b | 0x80000000u);
}
static __device__ __forceinline__ float dec_f(unsigned k) {
    return (k & 0x80000000u) ? __uint_as_float(k ^ 0x80000000u) : __uint_as_float(~k);
}

// ---------------- CSR build ----------------
__global__ void zero_csr_kernel(int n) {
    int i = blockIdx.x * blockDim.x + threadIdx.x;
    if (i < n) { d_deg[i] = 0; d_cnt2[i] = 0; }
    // merged pool-init (range far below n)
    if (i < GG * HIDN) { d_gsum[i] = 0.f; d_gmaxk[i] = 0u; }
    if (i < GG) d_gcnt[i] = 0;
}

__global__ void hist_kernel(const int* __restrict__ dst, int E) {
    int e = blockIdx.x * blockDim.x + threadIdx.x;
    if (e < E) atomicAdd(&d_deg[dst[e]], 1);
}

// single-block scan over d_deg -> exclusive offsets d_off
__global__ void scan_kernel(int n) {
    __shared__ int s[32];
    int tid = threadIdx.x, lane = tid & 31, wid = tid >> 5;
    int base = 0;
    if (tid == 0) d_off[0] = 0;
    for (int start = 0; start < n; start += 1024) {
        int i = start + tid;
        int v = (i < n) ? d_deg[i] : 0;
#pragma unroll
        for (int o = 1; o < 32; o <<= 1) {
            int t = __shfl_up_sync(0xffffffffu, v, o);
            if (lane >= o) v += t;
        }
        if (lane == 31) s[wid] = v;
        __syncthreads();
        if (wid == 0) {
            int w = s[lane];
#pragma unroll
            for (int o = 1; o < 32; o <<= 1) {
                int t = __shfl_up_sync(0xffffffffu, w, o);
                if (lane >= o) w += t;
            }
            s[lane] = w;
        }
        __syncthreads();
        int add = base + (wid ? s[wid - 1] : 0);
        v += add;
        if (i < n) d_off[i + 1] = v;
        base += s[31];
        __syncthreads();
    }
}

__global__ void scatter_kernel(const int* __restrict__ src, const int* __restrict__ dst, int E) {
    int e = blockIdx.x * blockDim.x + threadIdx.x;
    if (e >= E) return;
    int d = dst[e];
    int p = d_off[d] + atomicAdd(&d_cnt2[d], 1);
    d_srcPerm[p] = src[e];
    d_posOf[e] = p;
}

// edge projection: eaP[pos[e]] = edge_attr[e] @ W_ep + b_ep   (one warp per edge)
__global__ void ea_proj_kernel(const float* __restrict__ eattr,
                               const float* __restrict__ W_ep,
                               const float* __restrict__ b_ep, int E) {
    __shared__ float Ws[32][33];
    __shared__ float bs[32];
    int tid = threadIdx.x;
    for (int i = tid; i < 1024; i += blockDim.x) Ws[i >> 5][i & 31] = W_ep[i];
    if (tid < 32) bs[tid] = b_ep[tid];
    __syncthreads();
    int gw = (blockIdx.x * blockDim.x + tid) >> 5;
    int lane = tid & 31;
    if (gw >= E) return;
    float a = eattr[gw * 32 + lane];
    float acc = bs[lane];
#pragma unroll
    for (int c = 0; c < 32; c++)
        acc = fmaf(__shfl_sync(0xffffffffu, a, c), Ws[c][lane], acc);
    d_eaP[(size_t)d_posOf[gw] * 32 + lane] = acc;
}

// ---------------- GEMM: C[M,128] = A[M,128] @ W[128,128] + bias (round-1 verbatim; PROVEN, do not touch) ----------------
__global__ void __launch_bounds__(256) gemm128_kernel(const float* __restrict__ A,
                                                      const float* __restrict__ W,
                                                      const float* __restrict__ bias,
                                                      float* __restrict__ C, int M) {
    __shared__ float As[32][132];   // transposed: As[k][row]
    __shared__ float Bs[32][128];   // Bs[k][col]
    int tid = threadIdx.x;
    int tx = tid & 15, ty = tid >> 4;
    int rowbase = blockIdx.x * 128;
    int r0 = ty * 4, r1 = 64 + ty * 4;
    int c0 = tx * 4, c1 = 64 + tx * 4;

    float acc[8][8];
#pragma unroll
    for (int i = 0; i < 8; i++)
#pragma unroll
        for (int j = 0; j < 8; j++) acc[i][j] = 0.f;

    for (int kc = 0; kc < 128; kc += 32) {
#pragma unroll
        for (int i = 0; i < 4; i++) {
            int f = tid + i * 256;       // 0..1023 float4s
            int row = f >> 3;            // 0..127
            int kq = f & 7;
            float4 a = (rowbase + row < M) ? ld4(A + (size_t)(rowbase + row) * 128 + kc + kq * 4)
                                           : make_float4(0.f, 0.f, 0.f, 0.f);
            As[kq * 4 + 0][row] = a.x;
            As[kq * 4 + 1][row] = a.y;
            As[kq * 4 + 2][row] = a.z;
            As[kq * 4 + 3][row] = a.w;
        }
#pragma unroll
        for (int i = 0; i < 4; i++) {
            int f = tid + i * 256;
            int k = f >> 5;
            int cq = f & 31;
            *reinterpret_cast<float4*>(&Bs[k][cq * 4]) = ld4(W + (size_t)(kc + k) * 128 + cq * 4);
        }
        __syncthreads();
#pragma unroll
        for (int k = 0; k < 32; k++) {
            float4 a0 = *reinterpret_cast<float4*>(&As[k][r0]);
            float4 a1 = *reinterpret_cast<float4*>(&As[k][r1]);
            float4 b0 = *reinterpret_cast<float4*>(&Bs[k][c0]);
            float4 b1 = *reinterpret_cast<float4*>(&Bs[k][c1]);
            float av[8] = {a0.x, a0.y, a0.z, a0.w, a1.x, a1.y, a1.z, a1.w};
            float bv[8] = {b0.x, b0.y, b0.z, b0.w, b1.x, b1.y, b1.z, b1.w};
#pragma unroll
            for (int i = 0; i < 8; i++)
#pragma unroll
                for (int j = 0; j < 8; j++) acc[i][j] = fmaf(av[i], bv[j], acc[i][j]);
        }
        __syncthreads();
    }

    float4 bb0 = ld4(bias + c0), bb1 = ld4(bias + c1);
#pragma unroll
    for (int i = 0; i < 8; i++) {
        int row = rowbase + ((i < 4) ? (r0 + i) : (r1 + i - 4));
        if (row < M) {
            float4 o0 = make_float4(acc[i][0] + bb0.x, acc[i][1] + bb0.y, acc[i][2] + bb0.z, acc[i][3] + bb0.w);
            float4 o1 = make_float4(acc[i][4] + bb1.x, acc[i][5] + bb1.y, acc[i][6] + bb1.z, acc[i][7] + bb1.w);
            st4(C + (size_t)row * 128 + c0, o0);
            st4(C + (size_t)row * 128 + c1, o1);
        }
    }
}

// ---------------- T[n][h][c] = sum_d q[n,h*32+d] * We[c][h*32+d];  B[n][h] = sum_d q*be ----------------
__global__ void t_kernel(const float* __restrict__ q,
                         const float* __restrict__ We_l,
                         const float* __restrict__ be_l, int n) {
    __shared__ float WeT[128][36];  // WeT[j][c]
    int tid = threadIdx.x;
    for (int i = tid; i < 32 * 128; i += blockDim.x) {
        int c = i >> 7, j = i & 127;
        WeT[j][c] = We_l[i];
    }
    __syncthreads();
    int gw = (blockIdx.x * blockDim.x + tid) >> 5;
    int lane = tid & 31;
    if (gw >= n) return;
    int h = lane >> 3, cl = lane & 7;
    float4 qv = ld4(q + (size_t)gw * 128 + lane * 4);
    float4 be4 = ld4(be_l + lane * 4);
    float bp = qv.x * be4.x + qv.y * be4.y + qv.z * be4.z + qv.w * be4.w;
    bp += __shfl_xor_sync(0xffffffffu, bp, 1);
    bp += __shfl_xor_sync(0xffffffffu, bp, 2);
    bp += __shfl_xor_sync(0xffffffffu, bp, 4);
    if (cl == 0) d_T[(size_t)gw * TROW + 128 + h] = bp;

    float4 acc = make_float4(0.f, 0.f, 0.f, 0.f);
#pragma unroll
    for (int d4 = 0; d4 < 8; d4++) {
        int sl = h * 8 + d4;
        float q0 = __shfl_sync(0xffffffffu, qv.x, sl);
        float q1 = __shfl_sync(0xffffffffu, qv.y, sl);
        float q2 = __shfl_sync(0xffffffffu, qv.z, sl);
        float q3 = __shfl_sync(0xffffffffu, qv.w, sl);
        int jb = h * 32 + d4 * 4;
        float4 w0 = *reinterpret_cast<float4*>(&WeT[jb + 0][cl * 4]);
        float4 w1 = *reinterpret_cast<float4*>(&WeT[jb + 1][cl * 4]);
        float4 w2 = *reinterpret_cast<float4*>(&WeT[jb + 2][cl * 4]);
        float4 w3 = *reinterpret_cast<float4*>(&WeT[jb + 3][cl * 4]);
        acc.x = fmaf(q0, w0.x, acc.x); acc.y = fmaf(q0, w0.y, acc.y); acc.z = fmaf(q0, w0.z, acc.z); acc.w = fmaf(q0, w0.w, acc.w);
        acc.x = fmaf(q1, w1.x, acc.x); acc.y = fmaf(q1, w1.y, acc.y); acc.z = fmaf(q1, w1.z, acc.z); acc.w = fmaf(q1, w1.w, acc.w);
        acc.x = fmaf(q2, w2.x, acc.x); acc.y = fmaf(q2, w2.y, acc.y); acc.z = fmaf(q2, w2.z, acc.z); acc.w = fmaf(q2, w2.w, acc.w);
        acc.x = fmaf(q3, w3.x, acc.x); acc.y = fmaf(q3, w3.y, acc.y); acc.z = fmaf(q3, w3.z, acc.z); acc.w = fmaf(q3, w3.w, acc.w);
    }
    st4(&d_T[(size_t)gw * TROW + h * 32 + cl * 4], acc);
}

// ---------------- edge attention + aggregation: one warp per destination node,
// depth-2 software pipeline on the K/eaP/V loads (index prefetch alone gained 70us) ----------------
__global__ void edge_agg_kernel(int n) {
    int gw = (blockIdx.x * blockDim.x + threadIdx.x) >> 5;
    int lane = threadIdx.x & 31;
    if (gw >= n) return;
    int h = lane >> 3, cl = lane & 7;
    const float scale = 0.17677669529663687f;  // 1/sqrt(32)

    float4 qv = ld4(d_q + (size_t)gw * 128 + lane * 4);
    float4 Tv = ld4(d_T + (size_t)gw * TROW + h * 32 + cl * 4);
    float  Bh = d_T[(size_t)gw * TROW + 128 + h];
    float4 acc = make_float4(0.f, 0.f, 0.f, 0.f);

    int jb = d_off[gw], je = d_off[gw + 1];
    if (jb >= je) {
        st4(d_agg + (size_t)gw * 128 + lane * 4, acc);
        return;
    }

    // preload iteration jb
    int sA = d_srcPerm[jb];
    float4 kvA = ld4g(d_k + (size_t)sA * 128 + lane * 4);
    float4 evA = ld4g(d_eaP + (size_t)jb * 32 + cl * 4);
    float4 vvA = ld4g(d_v + (size_t)sA * 128 + lane * 4);

    for (int j = jb; j < je; j++) {
        // issue loads for j+1 before consuming j (MLP=2)
        int jn = (j + 1 < je) ? (j + 1) : j;
        int sB = d_srcPerm[jn];
        float4 kvB = ld4g(d_k + (size_t)sB * 128 + lane * 4);
        float4 evB = ld4g(d_eaP + (size_t)jn * 32 + cl * 4);
        float4 vvB = ld4g(d_v + (size_t)sB * 128 + lane * 4);

        float p = qv.x * kvA.x + qv.y * kvA.y + qv.z * kvA.z + qv.w * kvA.w
                + evA.x * Tv.x + evA.y * Tv.y + evA.z * Tv.z + evA.w * Tv.w;
        p += __shfl_xor_sync(0xffffffffu, p, 1);
        p += __shfl_xor_sync(0xffffffffu, p, 2);
        p += __shfl_xor_sync(0xffffffffu, p, 4);
        float amy = (p + Bh) * scale;
        float a0 = __shfl_sync(0xffffffffu, amy, 0);
        float a1 = __shfl_sync(0xffffffffu, amy, 8);
        float a2 = __shfl_sync(0xffffffffu, amy, 16);
        float a3 = __shfl_sync(0xffffffffu, amy, 24);
        float m = fmaxf(fmaxf(a0, a1), fmaxf(a2, a3));
        float e0 = __expf(a0 - m), e1 = __expf(a1 - m), e2 = __expf(a2 - m), e3 = __expf(a3 - m);
        float w = __expf(amy - m) / (e0 + e1 + e2 + e3);
        acc.x = fmaf(w, vvA.x, acc.x);
        acc.y = fmaf(w, vvA.y, acc.y);
        acc.z = fmaf(w, vvA.z, acc.z);
        acc.w = fmaf(w, vvA.w, acc.w);

        kvA = kvB; evA = evB; vvA = vvB;
    }
    st4(d_agg + (size_t)gw * 128 + lane * 4, acc);
}

// ---------------- h = LayerNorm(tmp + h) * g + b   (one warp per node) ----------------
__global__ void ln_kernel(float* __restrict__ h,
                          const float* __restrict__ g,
                          const float* __restrict__ b, int n) {
    int gw = (blockIdx.x * blockDim.x + threadIdx.x) >> 5;
    int lane = threadIdx.x & 31;
    if (gw >= n) return;
    float4 t = ld4(d_tmp + (size_t)gw * 128 + lane * 4);
    float4 hv = ld4(h + (size_t)gw * 128 + lane * 4);
    float4 s = make_float4(t.x + hv.x, t.y + hv.y, t.z + hv.z, t.w + hv.w);
    float sum = s.x + s.y + s.z + s.w;
#pragma unroll
    for (int o = 16; o >= 1; o >>= 1) sum += __shfl_xor_sync(0xffffffffu, sum, o);
    float mu = sum * (1.f / 128.f);
    float dx = s.x - mu, dy = s.y - mu, dz = s.z - mu, dw = s.w - mu;
    float sq = dx * dx + dy * dy + dz * dz + dw * dw;
#pragma unroll
    for (int o = 16; o >= 1; o >>= 1) sq += __shfl_xor_sync(0xffffffffu, sq, o);
    float inv = rsqrtf(sq * (1.f / 128.f) + 1e-5f);
    float4 gg = ld4(g + lane * 4), bb = ld4(b + lane * 4);
    float4 o4 = make_float4(dx * inv * gg.x + bb.x, dy * inv * gg.y + bb.y,
                            dz * inv * gg.z + bb.z, dw * inv * gg.w + bb.w);
    st4(h + (size_t)gw * 128 + lane * 4, o4);
}

// ---------------- pooling ----------------
#define NPB 256
__global__ void pool_kernel(const float* __restrict__ h, const int* __restrict__ batch, int n) {
    int c = threadIdx.x;  // 0..127
    int b0 = blockIdx.x * NPB;
    if (b0 >= n) return;
    int b1 = min(b0 + NPB, n);
    int g = batch[b0];
    float asum = 0.f, amax = -3.402823466e38f;
    int cnt = 0;
    for (int i = b0; i < b1; i++) {
        int gn = batch[i];
        if (gn != g) {
            atomicAdd(&d_gsum[g * HIDN + c], asum);
            atomicMax(&d_gmaxk[g * HIDN + c], enc_f(amax));
            if (c == 0) atomicAdd(&d_gcnt[g], cnt);
            g = gn; asum = 0.f; amax = -3.402823466e38f; cnt = 0;
        }
        float val = h[(size_t)i * HIDN + c];
        asum += val;
        amax = fmaxf(amax, val);
        cnt++;
    }
    atomicAdd(&d_gsum[g * HIDN + c], asum);
    atomicMax(&d_gmaxk[g * HIDN + c], enc_f(amax));
    if (c == 0) atomicAdd(&d_gcnt[g], cnt);
}

// ---------------- graph head: relu([mean|max|sum] @ W1 + b1) @ W2 + b2 ----------------
__global__ void mlp_kernel(const float* __restrict__ W1, const float* __restrict__ b1,
                           const float* __restrict__ W2, const float* __restrict__ b2,
                           float* __restrict__ gout) {
    __shared__ float pooled[384];
    __shared__ float t[128];
    int g = blockIdx.x, c = threadIdx.x;
    float cnt = fmaxf((float)d_gcnt[g], 1.f);
    float sv = d_gsum[g * HIDN + c];
    pooled[c] = sv / cnt;
    pooled[128 + c] = dec_f(d_gmaxk[g * HIDN + c]);
    pooled[256 + c] = sv;
    __syncthreads();
    float acc = b1[c];
#pragma unroll 8
    for (int kk = 0; kk < 384; kk++) acc = fmaf(pooled[kk], W1[kk * 128 + c], acc);
    t[c] = fmaxf(acc, 0.f);
    __syncthreads();
    float o = b2[c];
#pragma unroll 8
    for (int kk = 0; kk < 128; kk++) o = fmaf(t[kk], W2[kk * 128 + c], o);
    gout[g * 128 + c] = o;
}

// ---------------- driver ----------------
extern "C" void kernel_launch(void* const* d_in, const int* in_sizes, int n_in,
                              void* d_out, int out_size) {
    const float* x     = (const float*)d_in[0];
    const int*   ei    = (const int*)d_in[1];
    const float* eattr = (const float*)d_in[2];
    const int*   batch = (const int*)d_in[3];
    const float* W_in  = (const float*)d_in[4];
    const float* b_in  = (const float*)d_in[5];
    const float* Wq    = (const float*)d_in[6];
    const float* bq    = (const float*)d_in[7];
    const float* Wk    = (const float*)d_in[8];
    const float* bk    = (const float*)d_in[9];
    const float* Wv    = (const float*)d_in[10];
    const float* bv    = (const float*)d_in[11];
    const float* We    = (const float*)d_in[12];
    const float* be    = (const float*)d_in[13];
    const float* Wo    = (const float*)d_in[14];
    const float* bo    = (const float*)d_in[15];
    const float* ln_g  = (const float*)d_in[16];
    const float* ln_b  = (const float*)d_in[17];
    const float* W_ep  = (const float*)d_in[18];
    const float* b_ep  = (const float*)d_in[19];
    const float* W1    = (const float*)d_in[20];
    const float* b1    = (const float*)d_in[21];
    const float* W2    = (const float*)d_in[22];
    const float* b2    = (const float*)d_in[23];

    int N = in_sizes[0] / 128;
    int E = in_sizes[1] / 2;

    float* out  = (float*)d_out;
    float* h    = out;                       // [N,128] lives directly in d_out
    float* gout = out + (size_t)N * HIDN;    // [G,128]

    void *pq, *pk, *pv, *ptmp, *pagg;
    cudaGetSymbolAddress(&pq, d_q);
    cudaGetSymbolAddress(&pk, d_k);
    cudaGetSymbolAddress(&pv, d_v);
    cudaGetSymbolAddress(&ptmp, d_tmp);
    cudaGetSymbolAddress(&pagg, d_agg);

    const int* src = ei;
    const int* dst = ei + E;

    int gE = (E + 255) / 256;
    int gN = (N + 255) / 256;
    int gW = (N + 7) / 8;         // warp-per-node kernels, 256-thread blocks
    int gEW = (E + 7) / 8;        // warp-per-edge
    int gGemm = (N + 127) / 128;

    // CSR build + edge projection (layer-independent); zero_csr also does pool init
    zero_csr_kernel<<<gN, 256>>>(N);
    hist_kernel<<<gE, 256>>>(dst, E);
    scan_kernel<<<1, 1024>>>(N);
    scatter_kernel<<<gE, 256>>>(src, dst, E);
    ea_proj_kernel<<<gEW, 256>>>(eattr, W_ep, b_ep, E);

    // input projection: h = x @ W_in + b_in
    gemm128_kernel<<<gGemm, 256>>>(x, W_in, b_in, h, N);

    for (int l = 0; l < 3; l++) {
        const float* Wq_l = Wq + (size_t)l * 128 * 128;
        const float* Wk_l = Wk + (size_t)l * 128 * 128;
        const float* Wv_l = Wv + (size_t)l * 128 * 128;
        const float* Wo_l = Wo + (size_t)l * 128 * 128;
        const float* We_l = We + (size_t)l * 32 * 128;

        gemm128_kernel<<<gGemm, 256>>>(h, Wq_l, bq + l * 128, (float*)pq, N);
        gemm128_kernel<<<gGemm, 256>>>(h, Wk_l, bk + l * 128, (float*)pk, N);
        gemm128_kernel<<<gGemm, 256>>>(h, Wv_l, bv + l * 128, (float*)pv, N);
        t_kernel<<<gW, 256>>>((const float*)pq, We_l, be + l * 128, N);
        edge_agg_kernel<<<gW, 256>>>(N);
        gemm128_kernel<<<gGemm, 256>>>((const float*)pagg, Wo_l, bo + l * 128, (float*)ptmp, N);
        ln_kernel<<<gW, 256>>>(h, ln_g + l * 128, ln_b + l * 128, N);
    }

    pool_kernel<<<(N + NPB - 1) / NPB, 128>>>(h, batch, N);
    mlp_kernel<<<GG, 128>>>(W1, b1, W2, b2, gout);
}

// round 14
// speedup vs baseline: 1.0743x; 1.0743x over previous
#include <cuda_runtime.h>
#include <math.h>

#define NN 50000
#define EE 800000
#define HIDN 128
#define GG 64
#define TROW 132   // T row: 128 (T[h][c]) + 4 (B[h])

// ---------------- scratch (static device globals; no runtime allocation) ----------------
__device__ float d_qkv[3ull * NN * HIDN];      // q | k | v contiguous
__device__ float d_Wqkv[3 * 128 * 128];        // packed Wq|Wk|Wv for one layer
__device__ float d_bqkv[3 * 128];              // packed bq|bk|bv for one layer
__device__ float d_T[NN * TROW];
__device__ float d_tmp[NN * HIDN];
__device__ float d_agg[NN * HIDN];
__device__ float d_eaP[EE * 32];
__device__ int   d_deg[NN];
__device__ int   d_cnt2[NN];
__device__ int   d_off[NN + 1];
__device__ int   d_srcPerm[EE];
__device__ int   d_posOf[EE];
__device__ float d_gsum[GG * HIDN];
__device__ unsigned d_gmaxk[GG * HIDN];
__device__ int   d_gcnt[GG];

static __device__ __forceinline__ float4 ld4(const float* p) { return *reinterpret_cast<const float4*>(p); }
static __device__ __forceinline__ void st4(float* p, float4 v) { *reinterpret_cast<float4*>(p) = v; }

static __device__ __forceinline__ unsigned enc_f(float f) {
    unsigned b = __float_as_uint(f);
    return (b & 0x80000000u) ? ~b : (b | 0x80000000u);
}
static __device__ __forceinline__ float dec_f(unsigned k) {
    return (k & 0x80000000u) ? __uint_as_float(k ^ 0x80000000u) : __uint_as_float(~k);
}

// ---------------- CSR build ----------------
__global__ void zero_csr_kernel(int n) {
    int i = blockIdx.x * blockDim.x + threadIdx.x;
    if (i < n) { d_deg[i] = 0; d_cnt2[i] = 0; }
}

__global__ void hist_kernel(const int* __restrict__ dst, int E) {
    int e = blockIdx.x * blockDim.x + threadIdx.x;
    if (e < E) atomicAdd(&d_deg[dst[e]], 1);
}

// single-block scan over d_deg -> exclusive offsets d_off
__global__ void scan_kernel(int n) {
    __shared__ int s[32];
    int tid = threadIdx.x, lane = tid & 31, wid = tid >> 5;
    int base = 0;
    if (tid == 0) d_off[0] = 0;
    for (int start = 0; start < n; start += 1024) {
        int i = start + tid;
        int v = (i < n) ? d_deg[i] : 0;
#pragma unroll
        for (int o = 1; o < 32; o <<= 1) {
            int t = __shfl_up_sync(0xffffffffu, v, o);
            if (lane >= o) v += t;
        }
        if (lane == 31) s[wid] = v;
        __syncthreads();
        if (wid == 0) {
            int w = s[lane];
#pragma unroll
            for (int o = 1; o < 32; o <<= 1) {
                int t = __shfl_up_sync(0xffffffffu, w, o);
                if (lane >= o) w += t;
            }
            s[lane] = w;
        }
        __syncthreads();
        int add = base + (wid ? s[wid - 1] : 0);
        v += add;
        if (i < n) d_off[i + 1] = v;
        base += s[31];
        __syncthreads();
    }
}

__global__ void scatter_kernel(const int* __restrict__ src, const int* __restrict__ dst, int E) {
    int e = blockIdx.x * blockDim.x + threadIdx.x;
    if (e >= E) return;
    int d = dst[e];
    int p = d_off[d] + atomicAdd(&d_cnt2[d], 1);
    d_srcPerm[p] = src[e];
    d_posOf[e] = p;
}

// edge projection: eaP[pos[e]] = edge_attr[e] @ W_ep + b_ep   (one warp per edge)
__global__ void ea_proj_kernel(const float* __restrict__ eattr,
                               const float* __restrict__ W_ep,
                               const float* __restrict__ b_ep, int E) {
    __shared__ float Ws[32][33];
    __shared__ float bs[32];
    int tid = threadIdx.x;
    for (int i = tid; i < 1024; i += blockDim.x) Ws[i >> 5][i & 31] = W_ep[i];
    if (tid < 32) bs[tid] = b_ep[tid];
    __syncthreads();
    int gw = (blockIdx.x * blockDim.x + tid) >> 5;
    int lane = tid & 31;
    if (gw >= E) return;
    float a = eattr[gw * 32 + lane];
    float acc = bs[lane];
#pragma unroll
    for (int c = 0; c < 32; c++)
        acc = fmaf(__shfl_sync(0xffffffffu, a, c), Ws[c][lane], acc);
    d_eaP[(size_t)d_posOf[gw] * 32 + lane] = acc;
}

// pack Wq|Wk|Wv and bq|bk|bv for one layer into contiguous scratch
__global__ void pack_qkv_kernel(const float* __restrict__ Wq_l,
                                const float* __restrict__ Wk_l,
                                const float* __restrict__ Wv_l,
                                const float* __restrict__ bq_l,
                                const float* __restrict__ bk_l,
                                const float* __restrict__ bv_l) {
    int i = blockIdx.x * blockDim.x + threadIdx.x;
    if (i < 16384) {
        d_Wqkv[i]             = Wq_l[i];
        d_Wqkv[16384 + i]     = Wk_l[i];
        d_Wqkv[2 * 16384 + i] = Wv_l[i];
    }
    if (i < 128) {
        d_bqkv[i]       = bq_l[i];
        d_bqkv[128 + i] = bk_l[i];
        d_bqkv[256 + i] = bv_l[i];
    }
}

// ---------------- GEMM: C[M,128] = A[M,128] @ W[128,128] + bias (round-1 verbatim; PROVEN, do not touch) ----------------
__global__ void __launch_bounds__(256) gemm128_kernel(const float* __restrict__ A,
                                                      const float* __restrict__ W,
                                                      const float* __restrict__ bias,
                                                      float* __restrict__ C, int M) {
    __shared__ float As[32][132];   // transposed: As[k][row]
    __shared__ float Bs[32][128];   // Bs[k][col]
    int tid = threadIdx.x;
    int tx = tid & 15, ty = tid >> 4;
    int rowbase = blockIdx.x * 128;
    int r0 = ty * 4, r1 = 64 + ty * 4;
    int c0 = tx * 4, c1 = 64 + tx * 4;

    float acc[8][8];
#pragma unroll
    for (int i = 0; i < 8; i++)
#pragma unroll
        for (int j = 0; j < 8; j++) acc[i][j] = 0.f;

    for (int kc = 0; kc < 128; kc += 32) {
#pragma unroll
        for (int i = 0; i < 4; i++) {
            int f = tid + i * 256;       // 0..1023 float4s
            int row = f >> 3;            // 0..127
            int kq = f & 7;
            float4 a = (rowbase + row < M) ? ld4(A + (size_t)(rowbase + row) * 128 + kc + kq * 4)
                                           : make_float4(0.f, 0.f, 0.f, 0.f);
            As[kq * 4 + 0][row] = a.x;
            As[kq * 4 + 1][row] = a.y;
            As[kq * 4 + 2][row] = a.z;
            As[kq * 4 + 3][row] = a.w;
        }
#pragma unroll
        for (int i = 0; i < 4; i++) {
            int f = tid + i * 256;
            int k = f >> 5;
            int cq = f & 31;
            *reinterpret_cast<float4*>(&Bs[k][cq * 4]) = ld4(W + (size_t)(kc + k) * 128 + cq * 4);
        }
        __syncthreads();
#pragma unroll
        for (int k = 0; k < 32; k++) {
            float4 a0 = *reinterpret_cast<float4*>(&As[k][r0]);
            float4 a1 = *reinterpret_cast<float4*>(&As[k][r1]);
            float4 b0 = *reinterpret_cast<float4*>(&Bs[k][c0]);
            float4 b1 = *reinterpret_cast<float4*>(&Bs[k][c1]);
            float av[8] = {a0.x, a0.y, a0.z, a0.w, a1.x, a1.y, a1.z, a1.w};
            float bv[8] = {b0.x, b0.y, b0.z, b0.w, b1.x, b1.y, b1.z, b1.w};
#pragma unroll
            for (int i = 0; i < 8; i++)
#pragma unroll
                for (int j = 0; j < 8; j++) acc[i][j] = fmaf(av[i], bv[j], acc[i][j]);
        }
        __syncthreads();
    }

    float4 bb0 = ld4(bias + c0), bb1 = ld4(bias + c1);
#pragma unroll
    for (int i = 0; i < 8; i++) {
        int row = rowbase + ((i < 4) ? (r0 + i) : (r1 + i - 4));
        if (row < M) {
            float4 o0 = make_float4(acc[i][0] + bb0.x, acc[i][1] + bb0.y, acc[i][2] + bb0.z, acc[i][3] + bb0.w);
            float4 o1 = make_float4(acc[i][4] + bb1.x, acc[i][5] + bb1.y, acc[i][6] + bb1.z, acc[i][7] + bb1.w);
            st4(C + (size_t)row * 128 + c0, o0);
            st4(C + (size_t)row * 128 + c1, o1);
        }
    }
}

// merged QKV GEMM: grid.x = 3*tilesPerMat; W/bias/C derived by UNIFORM ARITHMETIC
// offsets from single bases (no pointer ternaries — those spilled in round 8).
// Body is otherwise verbatim gemm128_kernel.
__global__ void __launch_bounds__(256) qkv_gemm_kernel(const float* __restrict__ A,
                                                       int tilesPerMat, int M) {
    __shared__ float As[32][132];
    __shared__ float Bs[32][128];
    int tid = threadIdx.x;
    int tx = tid & 15, ty = tid >> 4;
    int which = blockIdx.x / tilesPerMat;
    int rowbase = (blockIdx.x - which * tilesPerMat) * 128;
    const float* W = d_Wqkv + which * 16384;
    const float* bias = d_bqkv + which * 128;
    float* C = d_qkv + (size_t)which * NN * HIDN;
    int r0 = ty * 4, r1 = 64 + ty * 4;
    int c0 = tx * 4, c1 = 64 + tx * 4;

    float acc[8][8];
#pragma unroll
    for (int i = 0; i < 8; i++)
#pragma unroll
        for (int j = 0; j < 8; j++) acc[i][j] = 0.f;

    for (int kc = 0; kc < 128; kc += 32) {
#pragma unroll
        for (int i = 0; i < 4; i++) {
            int f = tid + i * 256;
            int row = f >> 3;
            int kq = f & 7;
            float4 a = (rowbase + row < M) ? ld4(A + (size_t)(rowbase + row) * 128 + kc + kq * 4)
                                           : make_float4(0.f, 0.f, 0.f, 0.f);
            As[kq * 4 + 0][row] = a.x;
            As[kq * 4 + 1][row] = a.y;
            As[kq * 4 + 2][row] = a.z;
            As[kq * 4 + 3][row] = a.w;
        }
#pragma unroll
        for (int i = 0; i < 4; i++) {
            int f = tid + i * 256;
            int k = f >> 5;
            int cq = f & 31;
            *reinterpret_cast<float4*>(&Bs[k][cq * 4]) = ld4(W + (size_t)(kc + k) * 128 + cq * 4);
        }
        __syncthreads();
#pragma unroll
        for (int k = 0; k < 32; k++) {
            float4 a0 = *reinterpret_cast<float4*>(&As[k][r0]);
            float4 a1 = *reinterpret_cast<float4*>(&As[k][r1]);
            float4 b0 = *reinterpret_cast<float4*>(&Bs[k][c0]);
            float4 b1 = *reinterpret_cast<float4*>(&Bs[k][c1]);
            float av[8] = {a0.x, a0.y, a0.z, a0.w, a1.x, a1.y, a1.z, a1.w};
            float bv[8] = {b0.x, b0.y, b0.z, b0.w, b1.x, b1.y, b1.z, b1.w};
#pragma unroll
            for (int i = 0; i < 8; i++)
#pragma unroll
                for (int j = 0; j < 8; j++) acc[i][j] = fmaf(av[i], bv[j], acc[i][j]);
        }
        __syncthreads();
    }

    float4 bb0 = ld4(bias + c0), bb1 = ld4(bias + c1);
#pragma unroll
    for (int i = 0; i < 8; i++) {
        int row = rowbase + ((i < 4) ? (r0 + i) : (r1 + i - 4));
        if (row < M) {
            float4 o0 = make_float4(acc[i][0] + bb0.x, acc[i][1] + bb0.y, acc[i][2] + bb0.z, acc[i][3] + bb0.w);
            float4 o1 = make_float4(acc[i][4] + bb1.x, acc[i][5] + bb1.y, acc[i][6] + bb1.z, acc[i][7] + bb1.w);
            st4(C + (size_t)row * 128 + c0, o0);
            st4(C + (size_t)row * 128 + c1, o1);
        }
    }
}

// ---------------- T[n][h][c] = sum_d q[n,h*32+d] * We[c][h*32+d];  B[n][h] = sum_d q*be ----------------
__global__ void t_kernel(const float* __restrict__ q,
                         const float* __restrict__ We_l,
                         const float* __restrict__ be_l, int n) {
    __shared__ float WeT[128][36];  // WeT[j][c]
    int tid = threadIdx.x;
    for (int i = tid; i < 32 * 128; i += blockDim.x) {
        int c = i >> 7, j = i & 127;
        WeT[j][c] = We_l[i];
    }
    __syncthreads();
    int gw = (blockIdx.x * blockDim.x + tid) >> 5;
    int lane = tid & 31;
    if (gw >= n) return;
    int h = lane >> 3, cl = lane & 7;
    float4 qv = ld4(q + (size_t)gw * 128 + lane * 4);
    float4 be4 = ld4(be_l + lane * 4);
    float bp = qv.x * be4.x + qv.y * be4.y + qv.z * be4.z + qv.w * be4.w;
    bp += __shfl_xor_sync(0xffffffffu, bp, 1);
    bp += __shfl_xor_sync(0xffffffffu, bp, 2);
    bp += __shfl_xor_sync(0xffffffffu, bp, 4);
    if (cl == 0) d_T[(size_t)gw * TROW + 128 + h] = bp;

    float4 acc = make_float4(0.f, 0.f, 0.f, 0.f);
#pragma unroll
    for (int d4 = 0; d4 < 8; d4++) {
        int sl = h * 8 + d4;
        float q0 = __shfl_sync(0xffffffffu, qv.x, sl);
        float q1 = __shfl_sync(0xffffffffu, qv.y, sl);
        float q2 = __shfl_sync(0xffffffffu, qv.z, sl);
        float q3 = __shfl_sync(0xffffffffu, qv.w, sl);
        int jb = h * 32 + d4 * 4;
        float4 w0 = *reinterpret_cast<float4*>(&WeT[jb + 0][cl * 4]);
        float4 w1 = *reinterpret_cast<float4*>(&WeT[jb + 1][cl * 4]);
        float4 w2 = *reinterpret_cast<float4*>(&WeT[jb + 2][cl * 4]);
        float4 w3 = *reinterpret_cast<float4*>(&WeT[jb + 3][cl * 4]);
        acc.x = fmaf(q0, w0.x, acc.x); acc.y = fmaf(q0, w0.y, acc.y); acc.z = fmaf(q0, w0.z, acc.z); acc.w = fmaf(q0, w0.w, acc.w);
        acc.x = fmaf(q1, w1.x, acc.x); acc.y = fmaf(q1, w1.y, acc.y); acc.z = fmaf(q1, w1.z, acc.z); acc.w = fmaf(q1, w1.w, acc.w);
        acc.x = fmaf(q2, w2.x, acc.x); acc.y = fmaf(q2, w2.y, acc.y); acc.z = fmaf(q2, w2.z, acc.z); acc.w = fmaf(q2, w2.w, acc.w);
        acc.x = fmaf(q3, w3.x, acc.x); acc.y = fmaf(q3, w3.y, acc.y); acc.z = fmaf(q3, w3.z, acc.z); acc.w = fmaf(q3, w3.w, acc.w);
    }
    st4(&d_T[(size_t)gw * TROW + h * 32 + cl * 4], acc);
}

// ---------------- edge attention + aggregation: one warp per destination node (round-9 proven form) ----------------
__global__ void edge_agg_kernel(int n) {
    int gw = (blockIdx.x * blockDim.x + threadIdx.x) >> 5;
    int lane = threadIdx.x & 31;
    if (gw >= n) return;
    int h = lane >> 3, cl = lane & 7;
    const float scale = 0.17677669529663687f;  // 1/sqrt(32)

    const float* kbase = d_qkv + (size_t)NN * HIDN;
    const float* vbase = d_qkv + 2ull * NN * HIDN;

    float4 qv = ld4(d_qkv + (size_t)gw * 128 + lane * 4);
    float4 Tv = ld4(d_T + (size_t)gw * TROW + h * 32 + cl * 4);
    float  Bh = d_T[(size_t)gw * TROW + 128 + h];
    float4 acc = make_float4(0.f, 0.f, 0.f, 0.f);

    int jb = d_off[gw], je = d_off[gw + 1];
    int s = (jb < je) ? d_srcPerm[jb] : 0;
    for (int j = jb; j < je; j++) {
        int s_next = (j + 1 < je) ? d_srcPerm[j + 1] : 0;   // prefetch next src idx
        float4 kv = ld4(kbase + (size_t)s * 128 + lane * 4);
        float4 ev = ld4(d_eaP + (size_t)j * 32 + cl * 4);
        float4 vv = ld4(vbase + (size_t)s * 128 + lane * 4);
        float p = qv.x * kv.x + qv.y * kv.y + qv.z * kv.z + qv.w * kv.w
                + ev.x * Tv.x + ev.y * Tv.y + ev.z * Tv.z + ev.w * Tv.w;
        p += __shfl_xor_sync(0xffffffffu, p, 1);
        p += __shfl_xor_sync(0xffffffffu, p, 2);
        p += __shfl_xor_sync(0xffffffffu, p, 4);
        float amy = (p + Bh) * scale;
        float a0 = __shfl_sync(0xffffffffu, amy, 0);
        float a1 = __shfl_sync(0xffffffffu, amy, 8);
        float a2 = __shfl_sync(0xffffffffu, amy, 16);
        float a3 = __shfl_sync(0xffffffffu, amy, 24);
        float m = fmaxf(fmaxf(a0, a1), fmaxf(a2, a3));
        float e0 = __expf(a0 - m), e1 = __expf(a1 - m), e2 = __expf(a2 - m), e3 = __expf(a3 - m);
        float w = __expf(amy - m) / (e0 + e1 + e2 + e3);
        acc.x = fmaf(w, vv.x, acc.x);
        acc.y = fmaf(w, vv.y, acc.y);
        acc.z = fmaf(w, vv.z, acc.z);
        acc.w = fmaf(w, vv.w, acc.w);
        s = s_next;
    }
    st4(d_agg + (size_t)gw * 128 + lane * 4, acc);
}

// ---------------- h = LayerNorm(tmp + h) * g + b   (one warp per node) ----------------
__global__ void ln_kernel(float* __restrict__ h,
                          const float* __restrict__ g,
                          const float* __restrict__ b, int n) {
    int gw = (blockIdx.x * blockDim.x + threadIdx.x) >> 5;
    int lane = threadIdx.x & 31;
    if (gw >= n) return;
    float4 t = ld4(d_tmp + (size_t)gw * 128 + lane * 4);
    float4 hv = ld4(h + (size_t)gw * 128 + lane * 4);
    float4 s = make_float4(t.x + hv.x, t.y + hv.y, t.z + hv.z, t.w + hv.w);
    float sum = s.x + s.y + s.z + s.w;
#pragma unroll
    for (int o = 16; o >= 1; o >>= 1) sum += __shfl_xor_sync(0xffffffffu, sum, o);
    float mu = sum * (1.f / 128.f);
    float dx = s.x - mu, dy = s.y - mu, dz = s.z - mu, dw = s.w - mu;
    float sq = dx * dx + dy * dy + dz * dz + dw * dw;
#pragma unroll
    for (int o = 16; o >= 1; o >>= 1) sq += __shfl_xor_sync(0xffffffffu, sq, o);
    float inv = rsqrtf(sq * (1.f / 128.f) + 1e-5f);
    float4 gg = ld4(g + lane * 4), bb = ld4(b + lane * 4);
    float4 o4 = make_float4(dx * inv * gg.x + bb.x, dy * inv * gg.y + bb.y,
                            dz * inv * gg.z + bb.z, dw * inv * gg.w + bb.w);
    st4(h + (size_t)gw * 128 + lane * 4, o4);
}

// ---------------- pooling ----------------
__global__ void pool_init_kernel() {
    int i = blockIdx.x * blockDim.x + threadIdx.x;
    if (i < GG * HIDN) { d_gsum[i] = 0.f; d_gmaxk[i] = 0u; }
    if (i < GG) d_gcnt[i] = 0;
}

#define NPB 256
__global__ void pool_kernel(const float* __restrict__ h, const int* __restrict__ batch, int n) {
    int c = threadIdx.x;  // 0..127
    int b0 = blockIdx.x * NPB;
    if (b0 >= n) return;
    int b1 = min(b0 + NPB, n);
    int g = batch[b0];
    float asum = 0.f, amax = -3.402823466e38f;
    int cnt = 0;
    for (int i = b0; i < b1; i++) {
        int gn = batch[i];
        if (gn != g) {
            atomicAdd(&d_gsum[g * HIDN + c], asum);
            atomicMax(&d_gmaxk[g * HIDN + c], enc_f(amax));
            if (c == 0) atomicAdd(&d_gcnt[g], cnt);
            g = gn; asum = 0.f; amax = -3.402823466e38f; cnt = 0;
        }
        float val = h[(size_t)i * HIDN + c];
        asum += val;
        amax = fmaxf(amax, val);
        cnt++;
    }
    atomicAdd(&d_gsum[g * HIDN + c], asum);
    atomicMax(&d_gmaxk[g * HIDN + c], enc_f(amax));
    if (c == 0) atomicAdd(&d_gcnt[g], cnt);
}

// ---------------- graph head: relu([mean|max|sum] @ W1 + b1) @ W2 + b2 ----------------
__global__ void mlp_kernel(const float* __restrict__ W1, const float* __restrict__ b1,
                           const float* __restrict__ W2, const float* __restrict__ b2,
                           float* __restrict__ gout) {
    __shared__ float pooled[384];
    __shared__ float t[128];
    int g = blockIdx.x, c = threadIdx.x;
    float cnt = fmaxf((float)d_gcnt[g], 1.f);
    float sv = d_gsum[g * HIDN + c];
    pooled[c] = sv / cnt;
    pooled[128 + c] = dec_f(d_gmaxk[g * HIDN + c]);
    pooled[256 + c] = sv;
    __syncthreads();
    float acc = b1[c];
#pragma unroll 8
    for (int kk = 0; kk < 384; kk++) acc = fmaf(pooled[kk], W1[kk * 128 + c], acc);
    t[c] = fmaxf(acc, 0.f);
    __syncthreads();
    float o = b2[c];
#pragma unroll 8
    for (int kk = 0; kk < 128; kk++) o = fmaf(t[kk], W2[kk * 128 + c], o);
    gout[g * 128 + c] = o;
}

// ---------------- driver ----------------
extern "C" void kernel_launch(void* const* d_in, const int* in_sizes, int n_in,
                              void* d_out, int out_size) {
    const float* x     = (const float*)d_in[0];
    const int*   ei    = (const int*)d_in[1];
    const float* eattr = (const float*)d_in[2];
    const int*   batch = (const int*)d_in[3];
    const float* W_in  = (const float*)d_in[4];
    const float* b_in  = (const float*)d_in[5];
    const float* Wq    = (const float*)d_in[6];
    const float* bq    = (const float*)d_in[7];
    const float* Wk    = (const float*)d_in[8];
    const float* bk    = (const float*)d_in[9];
    const float* Wv    = (const float*)d_in[10];
    const float* bv    = (const float*)d_in[11];
    const float* We    = (const float*)d_in[12];
    const float* be    = (const float*)d_in[13];
    const float* Wo    = (const float*)d_in[14];
    const float* bo    = (const float*)d_in[15];
    const float* ln_g  = (const float*)d_in[16];
    const float* ln_b  = (const float*)d_in[17];
    const float* W_ep  = (const float*)d_in[18];
    const float* b_ep  = (const float*)d_in[19];
    const float* W1    = (const float*)d_in[20];
    const float* b1    = (const float*)d_in[21];
    const float* W2    = (const float*)d_in[22];
    const float* b2    = (const float*)d_in[23];

    int N = in_sizes[0] / 128;
    int E = in_sizes[1] / 2;

    float* out  = (float*)d_out;
    float* h    = out;                       // [N,128] lives directly in d_out
    float* gout = out + (size_t)N * HIDN;    // [G,128]

    void *pqkv, *ptmp, *pagg;
    cudaGetSymbolAddress(&pqkv, d_qkv);
    cudaGetSymbolAddress(&ptmp, d_tmp);
    cudaGetSymbolAddress(&pagg, d_agg);

    const int* src = ei;
    const int* dst = ei + E;

    int gE = (E + 255) / 256;
    int gN = (N + 255) / 256;
    int gW = (N + 7) / 8;         // warp-per-node kernels, 256-thread blocks
    int gEW = (E + 7) / 8;        // warp-per-edge
    int gGemm = (N + 127) / 128;

    // CSR build + edge projection (layer-independent)
    zero_csr_kernel<<<gN, 256>>>(N);
    hist_kernel<<<gE, 256>>>(dst, E);
    scan_kernel<<<1, 1024>>>(N);
    scatter_kernel<<<gE, 256>>>(src, dst, E);
    ea_proj_kernel<<<gEW, 256>>>(eattr, W_ep, b_ep, E);

    // input projection: h = x @ W_in + b_in
    gemm128_kernel<<<gGemm, 256>>>(x, W_in, b_in, h, N);

    for (int l = 0; l < 3; l++) {
        const float* Wq_l = Wq + (size_t)l * 128 * 128;
        const float* Wk_l = Wk + (size_t)l * 128 * 128;
        const float* Wv_l = Wv + (size_t)l * 128 * 128;
        const float* Wo_l = Wo + (size_t)l * 128 * 128;
        const float* We_l = We + (size_t)l * 32 * 128;

        pack_qkv_kernel<<<64, 256>>>(Wq_l, Wk_l, Wv_l,
                                     bq + l * 128, bk + l * 128, bv + l * 128);
        qkv_gemm_kernel<<<3 * gGemm, 256>>>(h, gGemm, N);
        t_kernel<<<gW, 256>>>((const float*)pqkv, We_l, be + l * 128, N);
        edge_agg_kernel<<<gW, 256>>>(N);
        gemm128_kernel<<<gGemm, 256>>>((const float*)pagg, Wo_l, bo + l * 128, (float*)ptmp, N);
        ln_kernel<<<gW, 256>>>(h, ln_g + l * 128, ln_b + l * 128, N);
    }

    pool_init_kernel<<<(GG * HIDN + 255) / 256, 256>>>();
    pool_kernel<<<(N + NPB - 1) / NPB, 128>>>(h, batch, N);
    mlp_kernel<<<GG, 128>>>(W1, b1, W2, b2, gout);
}

// round 15
// speedup vs baseline: 1.3128x; 1.2220x over previous
#include <cuda_runtime.h>
#include <math.h>

#define NN 50000
#define EE 800000
#define HIDN 128
#define GG 64
#define TROW 132   // T row: 128 (T[h][c]) + 4 (B[h])

// ---------------- scratch (static device globals; no runtime allocation) ----------------
__device__ float d_qkv[3ull * NN * HIDN];      // q | k | v contiguous
__device__ float d_Wqkv[3 * 128 * 128];        // packed Wq|Wk|Wv for one layer
__device__ float d_bqkv[3 * 128];              // packed bq|bk|bv for one layer
__device__ float d_T[NN * TROW];
__device__ float d_tmp[NN * HIDN];
__device__ float d_agg[NN * HIDN];
__device__ float d_eaP[EE * 32];
__device__ int   d_deg[NN];
__device__ int   d_cnt2[NN];
__device__ int   d_off[NN + 1];
__device__ int   d_srcPerm[EE];
__device__ int   d_posOf[EE];
__device__ float d_gsum[GG * HIDN];
__device__ unsigned d_gmaxk[GG * HIDN];
__device__ int   d_gcnt[GG];

static __device__ __forceinline__ float4 ld4(const float* p) { return *reinterpret_cast<const float4*>(p); }
static __device__ __forceinline__ void st4(float* p, float4 v) { *reinterpret_cast<float4*>(p) = v; }

static __device__ __forceinline__ unsigned enc_f(float f) {
    unsigned b = __float_as_uint(f);
    return (b & 0x80000000u) ? ~b : (b | 0x80000000u);
}
static __device__ __forceinline__ float dec_f(unsigned k) {
    return (k & 0x80000000u) ? __uint_as_float(k ^ 0x80000000u) : __uint_as_float(~k);
}

// round fp32 -> tf32 (rna) once, at smem-fill time
static __device__ __forceinline__ float tf32rf(float x) {
    unsigned y;
    asm("cvt.rna.tf32.f32 %0, %1;" : "=r"(y) : "f"(x));
    return __uint_as_float(y);
}
static __device__ __forceinline__ float4 tf32r4(float4 v) {
    v.x = tf32rf(v.x); v.y = tf32rf(v.y); v.z = tf32rf(v.z); v.w = tf32rf(v.w);
    return v;
}

#define MMA_TF32(d0,d1,d2,d3,a0,a1,a2,a3,b0,b1) \
    asm volatile("mma.sync.aligned.m16n8k8.row.col.f32.tf32.tf32.f32 " \
        "{%0,%1,%2,%3}, {%4,%5,%6,%7}, {%8,%9}, {%0,%1,%2,%3};" \
        : "+f"(d0), "+f"(d1), "+f"(d2), "+f"(d3) \
        : "r"(a0), "r"(a1), "r"(a2), "r"(a3), "r"(b0), "r"(b1))

// ---------------- CSR build ----------------
__global__ void zero_csr_kernel(int n) {
    int i = blockIdx.x * blockDim.x + threadIdx.x;
    if (i < n) { d_deg[i] = 0; d_cnt2[i] = 0; }
}

__global__ void hist_kernel(const int* __restrict__ dst, int E) {
    int e = blockIdx.x * blockDim.x + threadIdx.x;
    if (e < E) atomicAdd(&d_deg[dst[e]], 1);
}

// single-block scan over d_deg -> exclusive offsets d_off
__global__ void scan_kernel(int n) {
    __shared__ int s[32];
    int tid = threadIdx.x, lane = tid & 31, wid = tid >> 5;
    int base = 0;
    if (tid == 0) d_off[0] = 0;
    for (int start = 0; start < n; start += 1024) {
        int i = start + tid;
        int v = (i < n) ? d_deg[i] : 0;
#pragma unroll
        for (int o = 1; o < 32; o <<= 1) {
            int t = __shfl_up_sync(0xffffffffu, v, o);
            if (lane >= o) v += t;
        }
        if (lane == 31) s[wid] = v;
        __syncthreads();
        if (wid == 0) {
            int w = s[lane];
#pragma unroll
            for (int o = 1; o < 32; o <<= 1) {
                int t = __shfl_up_sync(0xffffffffu, w, o);
                if (lane >= o) w += t;
            }
            s[lane] = w;
        }
        __syncthreads();
        int add = base + (wid ? s[wid - 1] : 0);
        v += add;
        if (i < n) d_off[i + 1] = v;
        base += s[31];
        __syncthreads();
    }
}

__global__ void scatter_kernel(const int* __restrict__ src, const int* __restrict__ dst, int E) {
    int e = blockIdx.x * blockDim.x + threadIdx.x;
    if (e >= E) return;
    int d = dst[e];
    int p = d_off[d] + atomicAdd(&d_cnt2[d], 1);
    d_srcPerm[p] = src[e];
    d_posOf[e] = p;
}

// edge projection: eaP[pos[e]] = edge_attr[e] @ W_ep + b_ep   (one warp per edge)
__global__ void ea_proj_kernel(const float* __restrict__ eattr,
                               const float* __restrict__ W_ep,
                               const float* __restrict__ b_ep, int E) {
    __shared__ float Ws[32][33];
    __shared__ float bs[32];
    int tid = threadIdx.x;
    for (int i = tid; i < 1024; i += blockDim.x) Ws[i >> 5][i & 31] = W_ep[i];
    if (tid < 32) bs[tid] = b_ep[tid];
    __syncthreads();
    int gw = (blockIdx.x * blockDim.x + tid) >> 5;
    int lane = tid & 31;
    if (gw >= E) return;
    float a = eattr[gw * 32 + lane];
    float acc = bs[lane];
#pragma unroll
    for (int c = 0; c < 32; c++)
        acc = fmaf(__shfl_sync(0xffffffffu, a, c), Ws[c][lane], acc);
    d_eaP[(size_t)d_posOf[gw] * 32 + lane] = acc;
}

// pack Wq|Wk|Wv and bq|bk|bv for one layer into contiguous scratch
__global__ void pack_qkv_kernel(const float* __restrict__ Wq_l,
                                const float* __restrict__ Wk_l,
                                const float* __restrict__ Wv_l,
                                const float* __restrict__ bq_l,
                                const float* __restrict__ bk_l,
                                const float* __restrict__ bv_l) {
    int i = blockIdx.x * blockDim.x + threadIdx.x;
    if (i < 16384) {
        d_Wqkv[i]             = Wq_l[i];
        d_Wqkv[16384 + i]     = Wk_l[i];
        d_Wqkv[2 * 16384 + i] = Wv_l[i];
    }
    if (i < 128) {
        d_bqkv[i]       = bq_l[i];
        d_bqkv[128 + i] = bk_l[i];
        d_bqkv[256 + i] = bv_l[i];
    }
}

// ---------------- tf32 tensor-core GEMM: C[M,128] = A[M,128] @ W[128,128] + bias
// 128x128 block tile, 8 warps (4 M x 2 N), warp tile 32x64, m16n8k8 tf32 mma.
// Accumulators: 64 floats/thread (same as proven fp32 kernel). No helpers, no
// pointer ternaries (both trip the local-memory guard).
__global__ void __launch_bounds__(256) gemm128_tf32_kernel(const float* __restrict__ A,
                                                           const float* __restrict__ W,
                                                           const float* __restrict__ bias,
                                                           float* __restrict__ C, int M) {
    __shared__ float As[128][36];   // A rows x 32 k-cols (pad 36: frag loads conflict-free)
    __shared__ float Bs[32][136];   // k x 128 n-cols (pad 136: frag loads conflict-free)
    int tid = threadIdx.x;
    int lane = tid & 31, warp = tid >> 5;
    int g = lane >> 2, tig = lane & 3;
    int wm = (warp & 3) * 32;
    int wn = (warp >> 2) * 64;
    int rowbase = blockIdx.x * 128;

    float c[2][8][4];
#pragma unroll
    for (int mf = 0; mf < 2; mf++)
#pragma unroll
        for (int nf = 0; nf < 8; nf++)
#pragma unroll
            for (int e = 0; e < 4; e++) c[mf][nf][e] = 0.f;

    for (int kc = 0; kc < 128; kc += 32) {
#pragma unroll
        for (int i = 0; i < 4; i++) {
            int f = tid + i * 256;
            int row = f >> 3;
            int q = f & 7;
            float4 a = (rowbase + row < M) ? ld4(A + (size_t)(rowbase + row) * 128 + kc + q * 4)
                                           : make_float4(0.f, 0.f, 0.f, 0.f);
            st4(&As[row][q * 4], tf32r4(a));
        }
#pragma unroll
        for (int i = 0; i < 4; i++) {
            int f = tid + i * 256;
            int k = f >> 5;
            int cq = f & 31;
            float4 b = ld4(W + (size_t)(kc + k) * 128 + cq * 4);
            st4(&Bs[k][cq * 4], tf32r4(b));
        }
        __syncthreads();
#pragma unroll
        for (int ks = 0; ks < 4; ks++) {
            int k = ks * 8;
            unsigned af[2][4];
#pragma unroll
            for (int mf = 0; mf < 2; mf++) {
                int r = wm + mf * 16 + g;
                af[mf][0] = __float_as_uint(As[r][k + tig]);
                af[mf][1] = __float_as_uint(As[r + 8][k + tig]);
                af[mf][2] = __float_as_uint(As[r][k + tig + 4]);
                af[mf][3] = __float_as_uint(As[r + 8][k + tig + 4]);
            }
#pragma unroll
            for (int nf = 0; nf < 8; nf++) {
                int n = wn + nf * 8 + g;
                unsigned b0 = __float_as_uint(Bs[k + tig][n]);
                unsigned b1 = __float_as_uint(Bs[k + tig + 4][n]);
                MMA_TF32(c[0][nf][0], c[0][nf][1], c[0][nf][2], c[0][nf][3],
                         af[0][0], af[0][1], af[0][2], af[0][3], b0, b1);
                MMA_TF32(c[1][nf][0], c[1][nf][1], c[1][nf][2], c[1][nf][3],
                         af[1][0], af[1][1], af[1][2], af[1][3], b0, b1);
            }
        }
        __syncthreads();
    }

#pragma unroll
    for (int nf = 0; nf < 8; nf++) {
        int col = wn + nf * 8 + tig * 2;
        float2 bb = *reinterpret_cast<const float2*>(bias + col);
#pragma unroll
        for (int mf = 0; mf < 2; mf++) {
            int r0 = rowbase + wm + mf * 16 + g;
            int r1 = r0 + 8;
            if (r0 < M) {
                float2 o = make_float2(c[mf][nf][0] + bb.x, c[mf][nf][1] + bb.y);
                *reinterpret_cast<float2*>(C + (size_t)r0 * 128 + col) = o;
            }
            if (r1 < M) {
                float2 o = make_float2(c[mf][nf][2] + bb.x, c[mf][nf][3] + bb.y);
                *reinterpret_cast<float2*>(C + (size_t)r1 * 128 + col) = o;
            }
        }
    }
}

// merged QKV tf32 GEMM: grid.x = 3*tilesPerMat; W/bias/C by uniform arithmetic
// offsets (round-14 proven pattern). Body duplicated from gemm128_tf32_kernel.
__global__ void __launch_bounds__(256) qkv_gemm_tf32_kernel(const float* __restrict__ A,
                                                            int tilesPerMat, int M) {
    __shared__ float As[128][36];
    __shared__ float Bs[32][136];
    int tid = threadIdx.x;
    int lane = tid & 31, warp = tid >> 5;
    int g = lane >> 2, tig = lane & 3;
    int wm = (warp & 3) * 32;
    int wn = (warp >> 2) * 64;
    int which = blockIdx.x / tilesPerMat;
    int rowbase = (blockIdx.x - which * tilesPerMat) * 128;
    const float* W = d_Wqkv + which * 16384;
    const float* bias = d_bqkv + which * 128;
    float* C = d_qkv + (size_t)which * NN * HIDN;

    float c[2][8][4];
#pragma unroll
    for (int mf = 0; mf < 2; mf++)
#pragma unroll
        for (int nf = 0; nf < 8; nf++)
#pragma unroll
            for (int e = 0; e < 4; e++) c[mf][nf][e] = 0.f;

    for (int kc = 0; kc < 128; kc += 32) {
#pragma unroll
        for (int i = 0; i < 4; i++) {
            int f = tid + i * 256;
            int row = f >> 3;
            int q = f & 7;
            float4 a = (rowbase + row < M) ? ld4(A + (size_t)(rowbase + row) * 128 + kc + q * 4)
                                           : make_float4(0.f, 0.f, 0.f, 0.f);
            st4(&As[row][q * 4], tf32r4(a));
        }
#pragma unroll
        for (int i = 0; i < 4; i++) {
            int f = tid + i * 256;
            int k = f >> 5;
            int cq = f & 31;
            float4 b = ld4(W + (size_t)(kc + k) * 128 + cq * 4);
            st4(&Bs[k][cq * 4], tf32r4(b));
        }
        __syncthreads();
#pragma unroll
        for (int ks = 0; ks < 4; ks++) {
            int k = ks * 8;
            unsigned af[2][4];
#pragma unroll
            for (int mf = 0; mf < 2; mf++) {
                int r = wm + mf * 16 + g;
                af[mf][0] = __float_as_uint(As[r][k + tig]);
                af[mf][1] = __float_as_uint(As[r + 8][k + tig]);
                af[mf][2] = __float_as_uint(As[r][k + tig + 4]);
                af[mf][3] = __float_as_uint(As[r + 8][k + tig + 4]);
            }
#pragma unroll
            for (int nf = 0; nf < 8; nf++) {
                int n = wn + nf * 8 + g;
                unsigned b0 = __float_as_uint(Bs[k + tig][n]);
                unsigned b1 = __float_as_uint(Bs[k + tig + 4][n]);
                MMA_TF32(c[0][nf][0], c[0][nf][1], c[0][nf][2], c[0][nf][3],
                         af[0][0], af[0][1], af[0][2], af[0][3], b0, b1);
                MMA_TF32(c[1][nf][0], c[1][nf][1], c[1][nf][2], c[1][nf][3],
                         af[1][0], af[1][1], af[1][2], af[1][3], b0, b1);
            }
        }
        __syncthreads();
    }

#pragma unroll
    for (int nf = 0; nf < 8; nf++) {
        int col = wn + nf * 8 + tig * 2;
        float2 bb = *reinterpret_cast<const float2*>(bias + col);
#pragma unroll
        for (int mf = 0; mf < 2; mf++) {
            int r0 = rowbase + wm + mf * 16 + g;
            int r1 = r0 + 8;
            if (r0 < M) {
                float2 o = make_float2(c[mf][nf][0] + bb.x, c[mf][nf][1] + bb.y);
                *reinterpret_cast<float2*>(C + (size_t)r0 * 128 + col) = o;
            }
            if (r1 < M) {
                float2 o = make_float2(c[mf][nf][2] + bb.x, c[mf][nf][3] + bb.y);
                *reinterpret_cast<float2*>(C + (size_t)r1 * 128 + col) = o;
            }
        }
    }
}

// ---------------- T[n][h][c] = sum_d q[n,h*32+d] * We[c][h*32+d];  B[n][h] = sum_d q*be ----------------
__global__ void t_kernel(const float* __restrict__ q,
                         const float* __restrict__ We_l,
                         const float* __restrict__ be_l, int n) {
    __shared__ float WeT[128][36];  // WeT[j][c]
    int tid = threadIdx.x;
    for (int i = tid; i < 32 * 128; i += blockDim.x) {
        int c = i >> 7, j = i & 127;
        WeT[j][c] = We_l[i];
    }
    __syncthreads();
    int gw = (blockIdx.x * blockDim.x + tid) >> 5;
    int lane = tid & 31;
    if (gw >= n) return;
    int h = lane >> 3, cl = lane & 7;
    float4 qv = ld4(q + (size_t)gw * 128 + lane * 4);
    float4 be4 = ld4(be_l + lane * 4);
    float bp = qv.x * be4.x + qv.y * be4.y + qv.z * be4.z + qv.w * be4.w;
    bp += __shfl_xor_sync(0xffffffffu, bp, 1);
    bp += __shfl_xor_sync(0xffffffffu, bp, 2);
    bp += __shfl_xor_sync(0xffffffffu, bp, 4);
    if (cl == 0) d_T[(size_t)gw * TROW + 128 + h] = bp;

    float4 acc = make_float4(0.f, 0.f, 0.f, 0.f);
#pragma unroll
    for (int d4 = 0; d4 < 8; d4++) {
        int sl = h * 8 + d4;
        float q0 = __shfl_sync(0xffffffffu, qv.x, sl);
        float q1 = __shfl_sync(0xffffffffu, qv.y, sl);
        float q2 = __shfl_sync(0xffffffffu, qv.z, sl);
        float q3 = __shfl_sync(0xffffffffu, qv.w, sl);
        int jb = h * 32 + d4 * 4;
        float4 w0 = *reinterpret_cast<float4*>(&WeT[jb + 0][cl * 4]);
        float4 w1 = *reinterpret_cast<float4*>(&WeT[jb + 1][cl * 4]);
        float4 w2 = *reinterpret_cast<float4*>(&WeT[jb + 2][cl * 4]);
        float4 w3 = *reinterpret_cast<float4*>(&WeT[jb + 3][cl * 4]);
        acc.x = fmaf(q0, w0.x, acc.x); acc.y = fmaf(q0, w0.y, acc.y); acc.z = fmaf(q0, w0.z, acc.z); acc.w = fmaf(q0, w0.w, acc.w);
        acc.x = fmaf(q1, w1.x, acc.x); acc.y = fmaf(q1, w1.y, acc.y); acc.z = fmaf(q1, w1.z, acc.z); acc.w = fmaf(q1, w1.w, acc.w);
        acc.x = fmaf(q2, w2.x, acc.x); acc.y = fmaf(q2, w2.y, acc.y); acc.z = fmaf(q2, w2.z, acc.z); acc.w = fmaf(q2, w2.w, acc.w);
        acc.x = fmaf(q3, w3.x, acc.x); acc.y = fmaf(q3, w3.y, acc.y); acc.z = fmaf(q3, w3.z, acc.z); acc.w = fmaf(q3, w3.w, acc.w);
    }
    st4(&d_T[(size_t)gw * TROW + h * 32 + cl * 4], acc);
}

// ---------------- edge attention + aggregation: one warp per destination node (round-9 proven form) ----------------
__global__ void edge_agg_kernel(int n) {
    int gw = (blockIdx.x * blockDim.x + threadIdx.x) >> 5;
    int lane = threadIdx.x & 31;
    if (gw >= n) return;
    int h = lane >> 3, cl = lane & 7;
    const float scale = 0.17677669529663687f;  // 1/sqrt(32)

    const float* kbase = d_qkv + (size_t)NN * HIDN;
    const float* vbase = d_qkv + 2ull * NN * HIDN;

    float4 qv = ld4(d_qkv + (size_t)gw * 128 + lane * 4);
    float4 Tv = ld4(d_T + (size_t)gw * TROW + h * 32 + cl * 4);
    float  Bh = d_T[(size_t)gw * TROW + 128 + h];
    float4 acc = make_float4(0.f, 0.f, 0.f, 0.f);

    int jb = d_off[gw], je = d_off[gw + 1];
    int s = (jb < je) ? d_srcPerm[jb] : 0;
    for (int j = jb; j < je; j++) {
        int s_next = (j + 1 < je) ? d_srcPerm[j + 1] : 0;   // prefetch next src idx
        float4 kv = ld4(kbase + (size_t)s * 128 + lane * 4);
        float4 ev = ld4(d_eaP + (size_t)j * 32 + cl * 4);
        float4 vv = ld4(vbase + (size_t)s * 128 + lane * 4);
        float p = qv.x * kv.x + qv.y * kv.y + qv.z * kv.z + qv.w * kv.w
                + ev.x * Tv.x + ev.y * Tv.y + ev.z * Tv.z + ev.w * Tv.w;
        p += __shfl_xor_sync(0xffffffffu, p, 1);
        p += __shfl_xor_sync(0xffffffffu, p, 2);
        p += __shfl_xor_sync(0xffffffffu, p, 4);
        float amy = (p + Bh) * scale;
        float a0 = __shfl_sync(0xffffffffu, amy, 0);
        float a1 = __shfl_sync(0xffffffffu, amy, 8);
        float a2 = __shfl_sync(0xffffffffu, amy, 16);
        float a3 = __shfl_sync(0xffffffffu, amy, 24);
        float m = fmaxf(fmaxf(a0, a1), fmaxf(a2, a3));
        float e0 = __expf(a0 - m), e1 = __expf(a1 - m), e2 = __expf(a2 - m), e3 = __expf(a3 - m);
        float w = __expf(amy - m) / (e0 + e1 + e2 + e3);
        acc.x = fmaf(w, vv.x, acc.x);
        acc.y = fmaf(w, vv.y, acc.y);
        acc.z = fmaf(w, vv.z, acc.z);
        acc.w = fmaf(w, vv.w, acc.w);
        s = s_next;
    }
    st4(d_agg + (size_t)gw * 128 + lane * 4, acc);
}

// ---------------- h = LayerNorm(tmp + h) * g + b   (one warp per node) ----------------
__global__ void ln_kernel(float* __restrict__ h,
                          const float* __restrict__ g,
                          const float* __restrict__ b, int n) {
    int gw = (blockIdx.x * blockDim.x + threadIdx.x) >> 5;
    int lane = threadIdx.x & 31;
    if (gw >= n) return;
    float4 t = ld4(d_tmp + (size_t)gw * 128 + lane * 4);
    float4 hv = ld4(h + (size_t)gw * 128 + lane * 4);
    float4 s = make_float4(t.x + hv.x, t.y + hv.y, t.z + hv.z, t.w + hv.w);
    float sum = s.x + s.y + s.z + s.w;
#pragma unroll
    for (int o = 16; o >= 1; o >>= 1) sum += __shfl_xor_sync(0xffffffffu, sum, o);
    float mu = sum * (1.f / 128.f);
    float dx = s.x - mu, dy = s.y - mu, dz = s.z - mu, dw = s.w - mu;
    float sq = dx * dx + dy * dy + dz * dz + dw * dw;
#pragma unroll
    for (int o = 16; o >= 1; o >>= 1) sq += __shfl_xor_sync(0xffffffffu, sq, o);
    float inv = rsqrtf(sq * (1.f / 128.f) + 1e-5f);
    float4 gg = ld4(g + lane * 4), bb = ld4(b + lane * 4);
    float4 o4 = make_float4(dx * inv * gg.x + bb.x, dy * inv * gg.y + bb.y,
                            dz * inv * gg.z + bb.z, dw * inv * gg.w + bb.w);
    st4(h + (size_t)gw * 128 + lane * 4, o4);
}

// ---------------- pooling ----------------
__global__ void pool_init_kernel() {
    int i = blockIdx.x * blockDim.x + threadIdx.x;
    if (i < GG * HIDN) { d_gsum[i] = 0.f; d_gmaxk[i] = 0u; }
    if (i < GG) d_gcnt[i] = 0;
}

#define NPB 256
__global__ void pool_kernel(const float* __restrict__ h, const int* __restrict__ batch, int n) {
    int c = threadIdx.x;  // 0..127
    int b0 = blockIdx.x * NPB;
    if (b0 >= n) return;
    int b1 = min(b0 + NPB, n);
    int g = batch[b0];
    float asum = 0.f, amax = -3.402823466e38f;
    int cnt = 0;
    for (int i = b0; i < b1; i++) {
        int gn = batch[i];
        if (gn != g) {
            atomicAdd(&d_gsum[g * HIDN + c], asum);
            atomicMax(&d_gmaxk[g * HIDN + c], enc_f(amax));
            if (c == 0) atomicAdd(&d_gcnt[g], cnt);
            g = gn; asum = 0.f; amax = -3.402823466e38f; cnt = 0;
        }
        float val = h[(size_t)i * HIDN + c];
        asum += val;
        amax = fmaxf(amax, val);
        cnt++;
    }
    atomicAdd(&d_gsum[g * HIDN + c], asum);
    atomicMax(&d_gmaxk[g * HIDN + c], enc_f(amax));
    if (c == 0) atomicAdd(&d_gcnt[g], cnt);
}

// ---------------- graph head: relu([mean|max|sum] @ W1 + b1) @ W2 + b2 ----------------
__global__ void mlp_kernel(const float* __restrict__ W1, const float* __restrict__ b1,
                           const float* __restrict__ W2, const float* __restrict__ b2,
                           float* __restrict__ gout) {
    __shared__ float pooled[384];
    __shared__ float t[128];
    int g = blockIdx.x, c = threadIdx.x;
    float cnt = fmaxf((float)d_gcnt[g], 1.f);
    float sv = d_gsum[g * HIDN + c];
    pooled[c] = sv / cnt;
    pooled[128 + c] = dec_f(d_gmaxk[g * HIDN + c]);
    pooled[256 + c] = sv;
    __syncthreads();
    float acc = b1[c];
#pragma unroll 8
    for (int kk = 0; kk < 384; kk++) acc = fmaf(pooled[kk], W1[kk * 128 + c], acc);
    t[c] = fmaxf(acc, 0.f);
    __syncthreads();
    float o = b2[c];
#pragma unroll 8
    for (int kk = 0; kk < 128; kk++) o = fmaf(t[kk], W2[kk * 128 + c], o);
    gout[g * 128 + c] = o;
}

// ---------------- driver ----------------
extern "C" void kernel_launch(void* const* d_in, const int* in_sizes, int n_in,
                              void* d_out, int out_size) {
    const float* x     = (const float*)d_in[0];
    const int*   ei    = (const int*)d_in[1];
    const float* eattr = (const float*)d_in[2];
    const int*   batch = (const int*)d_in[3];
    const float* W_in  = (const float*)d_in[4];
    const float* b_in  = (const float*)d_in[5];
    const float* Wq    = (const float*)d_in[6];
    const float* bq    = (const float*)d_in[7];
    const float* Wk    = (const float*)d_in[8];
    const float* bk    = (const float*)d_in[9];
    const float* Wv    = (const float*)d_in[10];
    const float* bv    = (const float*)d_in[11];
    const float* We    = (const float*)d_in[12];
    const float* be    = (const float*)d_in[13];
    const float* Wo    = (const float*)d_in[14];
    const float* bo    = (const float*)d_in[15];
    const float* ln_g  = (const float*)d_in[16];
    const float* ln_b  = (const float*)d_in[17];
    const float* W_ep  = (const float*)d_in[18];
    const float* b_ep  = (const float*)d_in[19];
    const float* W1    = (const float*)d_in[20];
    const float* b1    = (const float*)d_in[21];
    const float* W2    = (const float*)d_in[22];
    const float* b2    = (const float*)d_in[23];

    int N = in_sizes[0] / 128;
    int E = in_sizes[1] / 2;

    float* out  = (float*)d_out;
    float* h    = out;                       // [N,128] lives directly in d_out
    float* gout = out + (size_t)N * HIDN;    // [G,128]

    void *pqkv, *ptmp, *pagg;
    cudaGetSymbolAddress(&pqkv, d_qkv);
    cudaGetSymbolAddress(&ptmp, d_tmp);
    cudaGetSymbolAddress(&pagg, d_agg);

    const int* src = ei;
    const int* dst = ei + E;

    int gE = (E + 255) / 256;
    int gN = (N + 255) / 256;
    int gW = (N + 7) / 8;         // warp-per-node kernels, 256-thread blocks
    int gEW = (E + 7) / 8;        // warp-per-edge
    int gGemm = (N + 127) / 128;

    // CSR build + edge projection (layer-independent)
    zero_csr_kernel<<<gN, 256>>>(N);
    hist_kernel<<<gE, 256>>>(dst, E);
    scan_kernel<<<1, 1024>>>(N);
    scatter_kernel<<<gE, 256>>>(src, dst, E);
    ea_proj_kernel<<<gEW, 256>>>(eattr, W_ep, b_ep, E);

    // input projection: h = x @ W_in + b_in
    gemm128_tf32_kernel<<<gGemm, 256>>>(x, W_in, b_in, h, N);

    for (int l = 0; l < 3; l++) {
        const float* Wq_l = Wq + (size_t)l * 128 * 128;
        const float* Wk_l = Wk + (size_t)l * 128 * 128;
        const float* Wv_l = Wv + (size_t)l * 128 * 128;
        const float* Wo_l = Wo + (size_t)l * 128 * 128;
        const float* We_l = We + (size_t)l * 32 * 128;

        pack_qkv_kernel<<<64, 256>>>(Wq_l, Wk_l, Wv_l,
                                     bq + l * 128, bk + l * 128, bv + l * 128);
        qkv_gemm_tf32_kernel<<<3 * gGemm, 256>>>(h, gGemm, N);
        t_kernel<<<gW, 256>>>((const float*)pqkv, We_l, be + l * 128, N);
        edge_agg_kernel<<<gW, 256>>>(N);
        gemm128_tf32_kernel<<<gGemm, 256>>>((const float*)pagg, Wo_l, bo + l * 128, (float*)ptmp, N);
        ln_kernel<<<gW, 256>>>(h, ln_g + l * 128, ln_b + l * 128, N);
    }

    pool_init_kernel<<<(GG * HIDN + 255) / 256, 256>>>();
    pool_kernel<<<(N + NPB - 1) / NPB, 128>>>(h, batch, N);
    mlp_kernel<<<GG, 128>>>(W1, b1, W2, b2, gout);
}

// round 17
// speedup vs baseline: 1.3300x; 1.0131x over previous
#include <cuda_runtime.h>
#include <math.h>

#define NN 50000
#define EE 800000
#define HIDN 128
#define GG 64
#define TROW 132   // T row: 128 (T[h][c]) + 4 (B[h])

// ---------------- scratch (static device globals; no runtime allocation) ----------------
__device__ float d_qkv[3ull * NN * HIDN];      // q | k | v contiguous
__device__ float d_Wqkv[3 * 128 * 128];        // packed Wq|Wk|Wv for one layer
__device__ float d_bqkv[3 * 128];              // packed bq|bk|bv for one layer
__device__ float d_T[NN * TROW];
__device__ float d_agg[NN * HIDN];
__device__ float d_eaP[EE * 32];
__device__ int   d_deg[NN];
__device__ int   d_cnt2[NN];
__device__ int   d_off[NN + 1];
__device__ int   d_srcPerm[EE];
__device__ int   d_posOf[EE];
__device__ float d_gsum[GG * HIDN];
__device__ unsigned d_gmaxk[GG * HIDN];
__device__ int   d_gcnt[GG];

static __device__ __forceinline__ float4 ld4(const float* p) { return *reinterpret_cast<const float4*>(p); }
static __device__ __forceinline__ void st4(float* p, float4 v) { *reinterpret_cast<float4*>(p) = v; }

static __device__ __forceinline__ unsigned enc_f(float f) {
    unsigned b = __float_as_uint(f);
    return (b & 0x80000000u) ? ~b : (b | 0x80000000u);
}
static __device__ __forceinline__ float dec_f(unsigned k) {
    return (k & 0x80000000u) ? __uint_as_float(k ^ 0x80000000u) : __uint_as_float(~k);
}

// round fp32 -> tf32 (rna) once, at smem-fill time
static __device__ __forceinline__ float tf32rf(float x) {
    unsigned y;
    asm("cvt.rna.tf32.f32 %0, %1;" : "=r"(y) : "f"(x));
    return __uint_as_float(y);
}
static __device__ __forceinline__ float4 tf32r4(float4 v) {
    v.x = tf32rf(v.x); v.y = tf32rf(v.y); v.z = tf32rf(v.z); v.w = tf32rf(v.w);
    return v;
}

#define MMA_TF32(d0,d1,d2,d3,a0,a1,a2,a3,b0,b1) \
    asm volatile("mma.sync.aligned.m16n8k8.row.col.f32.tf32.tf32.f32 " \
        "{%0,%1,%2,%3}, {%4,%5,%6,%7}, {%8,%9}, {%0,%1,%2,%3};" \
        : "+f"(d0), "+f"(d1), "+f"(d2), "+f"(d3) \
        : "r"(a0), "r"(a1), "r"(a2), "r"(a3), "r"(b0), "r"(b1))

// ---------------- CSR build (also does pool init; proven in round 12) ----------------
__global__ void zero_csr_kernel(int n) {
    int i = blockIdx.x * blockDim.x + threadIdx.x;
    if (i < n) { d_deg[i] = 0; d_cnt2[i] = 0; }
    if (i < GG * HIDN) { d_gsum[i] = 0.f; d_gmaxk[i] = 0u; }
    if (i < GG) d_gcnt[i] = 0;
}

__global__ void hist_kernel(const int* __restrict__ dst, int E) {
    int e = blockIdx.x * blockDim.x + threadIdx.x;
    if (e < E) atomicAdd(&d_deg[dst[e]], 1);
}

// single-block scan over d_deg -> exclusive offsets d_off
__global__ void scan_kernel(int n) {
    __shared__ int s[32];
    int tid = threadIdx.x, lane = tid & 31, wid = tid >> 5;
    int base = 0;
    if (tid == 0) d_off[0] = 0;
    for (int start = 0; start < n; start += 1024) {
        int i = start + tid;
        int v = (i < n) ? d_deg[i] : 0;
#pragma unroll
        for (int o = 1; o < 32; o <<= 1) {
            int t = __shfl_up_sync(0xffffffffu, v, o);
            if (lane >= o) v += t;
        }
        if (lane == 31) s[wid] = v;
        __syncthreads();
        if (wid == 0) {
            int w = s[lane];
#pragma unroll
            for (int o = 1; o < 32; o <<= 1) {
                int t = __shfl_up_sync(0xffffffffu, w, o);
                if (lane >= o) w += t;
            }
            s[lane] = w;
        }
        __syncthreads();
        int add = base + (wid ? s[wid - 1] : 0);
        v += add;
        if (i < n) d_off[i + 1] = v;
        base += s[31];
        __syncthreads();
    }
}

__global__ void scatter_kernel(const int* __restrict__ src, const int* __restrict__ dst, int E) {
    int e = blockIdx.x * blockDim.x + threadIdx.x;
    if (e >= E) return;
    int d = dst[e];
    int p = d_off[d] + atomicAdd(&d_cnt2[d], 1);
    d_srcPerm[p] = src[e];
    d_posOf[e] = p;
}

// edge projection: eaP[pos[e]] = edge_attr[e] @ W_ep + b_ep   (one warp per edge)
__global__ void ea_proj_kernel(const float* __restrict__ eattr,
                               const float* __restrict__ W_ep,
                               const float* __restrict__ b_ep, int E) {
    __shared__ float Ws[32][33];
    __shared__ float bs[32];
    int tid = threadIdx.x;
    for (int i = tid; i < 1024; i += blockDim.x) Ws[i >> 5][i & 31] = W_ep[i];
    if (tid < 32) bs[tid] = b_ep[tid];
    __syncthreads();
    int gw = (blockIdx.x * blockDim.x + tid) >> 5;
    int lane = tid & 31;
    if (gw >= E) return;
    float a = eattr[gw * 32 + lane];
    float acc = bs[lane];
#pragma unroll
    for (int c = 0; c < 32; c++)
        acc = fmaf(__shfl_sync(0xffffffffu, a, c), Ws[c][lane], acc);
    d_eaP[(size_t)d_posOf[gw] * 32 + lane] = acc;
}

// pack Wq|Wk|Wv and bq|bk|bv for one layer into contiguous scratch
__global__ void pack_qkv_kernel(const float* __restrict__ Wq_l,
                                const float* __restrict__ Wk_l,
                                const float* __restrict__ Wv_l,
                                const float* __restrict__ bq_l,
                                const float* __restrict__ bk_l,
                                const float* __restrict__ bv_l) {
    int i = blockIdx.x * blockDim.x + threadIdx.x;
    if (i < 16384) {
        d_Wqkv[i]             = Wq_l[i];
        d_Wqkv[16384 + i]     = Wk_l[i];
        d_Wqkv[2 * 16384 + i] = Wv_l[i];
    }
    if (i < 128) {
        d_bqkv[i]       = bq_l[i];
        d_bqkv[128 + i] = bk_l[i];
        d_bqkv[256 + i] = bv_l[i];
    }
}

// ---------------- tf32 tensor-core GEMM (round-15 proven): 8 warps 4Mx2N, warp tile 32x64 ----------------
__global__ void __launch_bounds__(256) gemm128_tf32_kernel(const float* __restrict__ A,
                                                           const float* __restrict__ W,
                                                           const float* __restrict__ bias,
                                                           float* __restrict__ C, int M) {
    __shared__ float As[128][36];
    __shared__ float Bs[32][136];
    int tid = threadIdx.x;
    int lane = tid & 31, warp = tid >> 5;
    int g = lane >> 2, tig = lane & 3;
    int wm = (warp & 3) * 32;
    int wn = (warp >> 2) * 64;
    int rowbase = blockIdx.x * 128;

    float c[2][8][4];
#pragma unroll
    for (int mf = 0; mf < 2; mf++)
#pragma unroll
        for (int nf = 0; nf < 8; nf++)
#pragma unroll
            for (int e = 0; e < 4; e++) c[mf][nf][e] = 0.f;

    for (int kc = 0; kc < 128; kc += 32) {
#pragma unroll
        for (int i = 0; i < 4; i++) {
            int f = tid + i * 256;
            int row = f >> 3;
            int q = f & 7;
            float4 a = (rowbase + row < M) ? ld4(A + (size_t)(rowbase + row) * 128 + kc + q * 4)
                                           : make_float4(0.f, 0.f, 0.f, 0.f);
            st4(&As[row][q * 4], tf32r4(a));
        }
#pragma unroll
        for (int i = 0; i < 4; i++) {
            int f = tid + i * 256;
            int k = f >> 5;
            int cq = f & 31;
            float4 b = ld4(W + (size_t)(kc + k) * 128 + cq * 4);
            st4(&Bs[k][cq * 4], tf32r4(b));
        }
        __syncthreads();
#pragma unroll
        for (int ks = 0; ks < 4; ks++) {
            int k = ks * 8;
            unsigned af[2][4];
#pragma unroll
            for (int mf = 0; mf < 2; mf++) {
                int r = wm + mf * 16 + g;
                af[mf][0] = __float_as_uint(As[r][k + tig]);
                af[mf][1] = __float_as_uint(As[r + 8][k + tig]);
                af[mf][2] = __float_as_uint(As[r][k + tig + 4]);
                af[mf][3] = __float_as_uint(As[r + 8][k + tig + 4]);
            }
#pragma unroll
            for (int nf = 0; nf < 8; nf++) {
                int n = wn + nf * 8 + g;
                unsigned b0 = __float_as_uint(Bs[k + tig][n]);
                unsigned b1 = __float_as_uint(Bs[k + tig + 4][n]);
                MMA_TF32(c[0][nf][0], c[0][nf][1], c[0][nf][2], c[0][nf][3],
                         af[0][0], af[0][1], af[0][2], af[0][3], b0, b1);
                MMA_TF32(c[1][nf][0], c[1][nf][1], c[1][nf][2], c[1][nf][3],
                         af[1][0], af[1][1], af[1][2], af[1][3], b0, b1);
            }
        }
        __syncthreads();
    }

#pragma unroll
    for (int nf = 0; nf < 8; nf++) {
        int col = wn + nf * 8 + tig * 2;
        float2 bb = *reinterpret_cast<const float2*>(bias + col);
#pragma unroll
        for (int mf = 0; mf < 2; mf++) {
            int r0 = rowbase + wm + mf * 16 + g;
            int r1 = r0 + 8;
            if (r0 < M) {
                float2 o = make_float2(c[mf][nf][0] + bb.x, c[mf][nf][1] + bb.y);
                *reinterpret_cast<float2*>(C + (size_t)r0 * 128 + col) = o;
            }
            if (r1 < M) {
                float2 o = make_float2(c[mf][nf][2] + bb.x, c[mf][nf][3] + bb.y);
                *reinterpret_cast<float2*>(C + (size_t)r1 * 128 + col) = o;
            }
        }
    }
}

// merged QKV tf32 GEMM (round-15 proven): uniform-offset multi-matrix
__global__ void __launch_bounds__(256) qkv_gemm_tf32_kernel(const float* __restrict__ A,
                                                            int tilesPerMat, int M) {
    __shared__ float As[128][36];
    __shared__ float Bs[32][136];
    int tid = threadIdx.x;
    int lane = tid & 31, warp = tid >> 5;
    int g = lane >> 2, tig = lane & 3;
    int wm = (warp & 3) * 32;
    int wn = (warp >> 2) * 64;
    int which = blockIdx.x / tilesPerMat;
    int rowbase = (blockIdx.x - which * tilesPerMat) * 128;
    const float* W = d_Wqkv + which * 16384;
    const float* bias = d_bqkv + which * 128;
    float* C = d_qkv + (size_t)which * NN * HIDN;

    float c[2][8][4];
#pragma unroll
    for (int mf = 0; mf < 2; mf++)
#pragma unroll
        for (int nf = 0; nf < 8; nf++)
#pragma unroll
            for (int e = 0; e < 4; e++) c[mf][nf][e] = 0.f;

    for (int kc = 0; kc < 128; kc += 32) {
#pragma unroll
        for (int i = 0; i < 4; i++) {
            int f = tid + i * 256;
            int row = f >> 3;
            int q = f & 7;
            float4 a = (rowbase + row < M) ? ld4(A + (size_t)(rowbase + row) * 128 + kc + q * 4)
                                           : make_float4(0.f, 0.f, 0.f, 0.f);
            st4(&As[row][q * 4], tf32r4(a));
        }
#pragma unroll
        for (int i = 0; i < 4; i++) {
            int f = tid + i * 256;
            int k = f >> 5;
            int cq = f & 31;
            float4 b = ld4(W + (size_t)(kc + k) * 128 + cq * 4);
            st4(&Bs[k][cq * 4], tf32r4(b));
        }
        __syncthreads();
#pragma unroll
        for (int ks = 0; ks < 4; ks++) {
            int k = ks * 8;
            unsigned af[2][4];
#pragma unroll
            for (int mf = 0; mf < 2; mf++) {
                int r = wm + mf * 16 + g;
                af[mf][0] = __float_as_uint(As[r][k + tig]);
                af[mf][1] = __float_as_uint(As[r + 8][k + tig]);
                af[mf][2] = __float_as_uint(As[r][k + tig + 4]);
                af[mf][3] = __float_as_uint(As[r + 8][k + tig + 4]);
            }
#pragma unroll
            for (int nf = 0; nf < 8; nf++) {
                int n = wn + nf * 8 + g;
                unsigned b0 = __float_as_uint(Bs[k + tig][n]);
                unsigned b1 = __float_as_uint(Bs[k + tig + 4][n]);
                MMA_TF32(c[0][nf][0], c[0][nf][1], c[0][nf][2], c[0][nf][3],
                         af[0][0], af[0][1], af[0][2], af[0][3], b0, b1);
                MMA_TF32(c[1][nf][0], c[1][nf][1], c[1][nf][2], c[1][nf][3],
                         af[1][0], af[1][1], af[1][2], af[1][3], b0, b1);
            }
        }
        __syncthreads();
    }

#pragma unroll
    for (int nf = 0; nf < 8; nf++) {
        int col = wn + nf * 8 + tig * 2;
        float2 bb = *reinterpret_cast<const float2*>(bias + col);
#pragma unroll
        for (int mf = 0; mf < 2; mf++) {
            int r0 = rowbase + wm + mf * 16 + g;
            int r1 = r0 + 8;
            if (r0 < M) {
                float2 o = make_float2(c[mf][nf][0] + bb.x, c[mf][nf][1] + bb.y);
                *reinterpret_cast<float2*>(C + (size_t)r0 * 128 + col) = o;
            }
            if (r1 < M) {
                float2 o = make_float2(c[mf][nf][2] + bb.x, c[mf][nf][3] + bb.y);
                *reinterpret_cast<float2*>(C + (size_t)r1 * 128 + col) = o;
            }
        }
    }
}

// ---------------- fused Wo tf32 GEMM + residual + LayerNorm: h = LN(agg@Wo + bo + h)*g + b
// ROW-OWNING warp tiling: 8 warps x 16 rows x 128 cols (16 N-frags, 1 M-frag), so
// each warp holds complete rows; LN reduces via 2 shfl_xor hops over the tig group.
// No pointer ternaries, no helpers.
__global__ void __launch_bounds__(256) gemm_ln_tf32_kernel(const float* __restrict__ A,
                                                           const float* __restrict__ W,
                                                           const float* __restrict__ bias,
                                                           const float* __restrict__ ln_g,
                                                           const float* __restrict__ ln_b,
                                                           float* __restrict__ h, int M) {
    __shared__ float As[128][36];
    __shared__ float Bs[32][136];
    int tid = threadIdx.x;
    int lane = tid & 31, warp = tid >> 5;
    int g = lane >> 2, tig = lane & 3;
    int wm = warp * 16;
    int rowbase = blockIdx.x * 128;

    float c[16][4];
#pragma unroll
    for (int nf = 0; nf < 16; nf++)
#pragma unroll
        for (int e = 0; e < 4; e++) c[nf][e] = 0.f;

    for (int kc = 0; kc < 128; kc += 32) {
#pragma unroll
        for (int i = 0; i < 4; i++) {
            int f = tid + i * 256;
            int row = f >> 3;
            int q = f & 7;
            float4 a = (rowbase + row < M) ? ld4(A + (size_t)(rowbase + row) * 128 + kc + q * 4)
                                           : make_float4(0.f, 0.f, 0.f, 0.f);
            st4(&As[row][q * 4], tf32r4(a));
        }
#pragma unroll
        for (int i = 0; i < 4; i++) {
            int f = tid + i * 256;
            int k = f >> 5;
            int cq = f & 31;
            float4 b = ld4(W + (size_t)(kc + k) * 128 + cq * 4);
            st4(&Bs[k][cq * 4], tf32r4(b));
        }
        __syncthreads();
#pragma unroll
        for (int ks = 0; ks < 4; ks++) {
            int k = ks * 8;
            int r = wm + g;
            unsigned a0 = __float_as_uint(As[r][k + tig]);
            unsigned a1 = __float_as_uint(As[r + 8][k + tig]);
            unsigned a2 = __float_as_uint(As[r][k + tig + 4]);
            unsigned a3 = __float_as_uint(As[r + 8][k + tig + 4]);
#pragma unroll
            for (int nf = 0; nf < 16; nf++) {
                int n = nf * 8 + g;
                unsigned b0 = __float_as_uint(Bs[k + tig][n]);
                unsigned b1 = __float_as_uint(Bs[k + tig + 4][n]);
                MMA_TF32(c[nf][0], c[nf][1], c[nf][2], c[nf][3], a0, a1, a2, a3, b0, b1);
            }
        }
        __syncthreads();
    }

    // epilogue: rows r0 = rowbase+wm+g (elems 0,1), r1 = r0+8 (elems 2,3)
    int r0 = rowbase + wm + g;
    int r1 = r0 + 8;
    bool ok0 = (r0 < M), ok1 = (r1 < M);
#pragma unroll
    for (int nf = 0; nf < 16; nf++) {
        int col = nf * 8 + tig * 2;
        float2 bb = *reinterpret_cast<const float2*>(bias + col);
        if (ok0) {
            float2 h0 = *reinterpret_cast<float2*>(h + (size_t)r0 * 128 + col);
            c[nf][0] += bb.x + h0.x;
            c[nf][1] += bb.y + h0.y;
        }
        if (ok1) {
            float2 h1 = *reinterpret_cast<float2*>(h + (size_t)r1 * 128 + col);
            c[nf][2] += bb.x + h1.x;
            c[nf][3] += bb.y + h1.y;
        }
    }
    float sum0 = 0.f, sum1 = 0.f;
#pragma unroll
    for (int nf = 0; nf < 16; nf++) {
        sum0 += c[nf][0] + c[nf][1];
        sum1 += c[nf][2] + c[nf][3];
    }
    sum0 += __shfl_xor_sync(0xffffffffu, sum0, 1);
    sum0 += __shfl_xor_sync(0xffffffffu, sum0, 2);
    sum1 += __shfl_xor_sync(0xffffffffu, sum1, 1);
    sum1 += __shfl_xor_sync(0xffffffffu, sum1, 2);
    float mu0 = sum0 * (1.f / 128.f), mu1 = sum1 * (1.f / 128.f);
    float sq0 = 0.f, sq1 = 0.f;
#pragma unroll
    for (int nf = 0; nf < 16; nf++) {
        c[nf][0] -= mu0; c[nf][1] -= mu0;
        c[nf][2] -= mu1; c[nf][3] -= mu1;
        sq0 = fmaf(c[nf][0], c[nf][0], sq0); sq0 = fmaf(c[nf][1], c[nf][1], sq0);
        sq1 = fmaf(c[nf][2], c[nf][2], sq1); sq1 = fmaf(c[nf][3], c[nf][3], sq1);
    }
    sq0 += __shfl_xor_sync(0xffffffffu, sq0, 1);
    sq0 += __shfl_xor_sync(0xffffffffu, sq0, 2);
    sq1 += __shfl_xor_sync(0xffffffffu, sq1, 1);
    sq1 += __shfl_xor_sync(0xffffffffu, sq1, 2);
    float inv0 = rsqrtf(sq0 * (1.f / 128.f) + 1e-5f);
    float inv1 = rsqrtf(sq1 * (1.f / 128.f) + 1e-5f);
#pragma unroll
    for (int nf = 0; nf < 16; nf++) {
        int col = nf * 8 + tig * 2;
        float2 gg = *reinterpret_cast<const float2*>(ln_g + col);
        float2 lb = *reinterpret_cast<const float2*>(ln_b + col);
        if (ok0) {
            float2 o = make_float2(c[nf][0] * inv0 * gg.x + lb.x, c[nf][1] * inv0 * gg.y + lb.y);
            *reinterpret_cast<float2*>(h + (size_t)r0 * 128 + col) = o;
        }
        if (ok1) {
            float2 o = make_float2(c[nf][2] * inv1 * gg.x + lb.x, c[nf][3] * inv1 * gg.y + lb.y);
            *reinterpret_cast<float2*>(h + (size_t)r1 * 128 + col) = o;
        }
    }
}

// ---------------- T[n][h][c] = sum_d q[n,h*32+d] * We[c][h*32+d];  B[n][h] = sum_d q*be ----------------
__global__ void t_kernel(const float* __restrict__ q,
                         const float* __restrict__ We_l,
                         const float* __restrict__ be_l, int n) {
    __shared__ float WeT[128][36];  // WeT[j][c]
    int tid = threadIdx.x;
    for (int i = tid; i < 32 * 128; i += blockDim.x) {
        int c = i >> 7, j = i & 127;
        WeT[j][c] = We_l[i];
    }
    __syncthreads();
    int gw = (blockIdx.x * blockDim.x + tid) >> 5;
    int lane = tid & 31;
    if (gw >= n) return;
    int h = lane >> 3, cl = lane & 7;
    float4 qv = ld4(q + (size_t)gw * 128 + lane * 4);
    float4 be4 = ld4(be_l + lane * 4);
    float bp = qv.x * be4.x + qv.y * be4.y + qv.z * be4.z + qv.w * be4.w;
    bp += __shfl_xor_sync(0xffffffffu, bp, 1);
    bp += __shfl_xor_sync(0xffffffffu, bp, 2);
    bp += __shfl_xor_sync(0xffffffffu, bp, 4);
    if (cl == 0) d_T[(size_t)gw * TROW + 128 + h] = bp;

    float4 acc = make_float4(0.f, 0.f, 0.f, 0.f);
#pragma unroll
    for (int d4 = 0; d4 < 8; d4++) {
        int sl = h * 8 + d4;
        float q0 = __shfl_sync(0xffffffffu, qv.x, sl);
        float q1 = __shfl_sync(0xffffffffu, qv.y, sl);
        float q2 = __shfl_sync(0xffffffffu, qv.z, sl);
        float q3 = __shfl_sync(0xffffffffu, qv.w, sl);
        int jb = h * 32 + d4 * 4;
        float4 w0 = *reinterpret_cast<float4*>(&WeT[jb + 0][cl * 4]);
        float4 w1 = *reinterpret_cast<float4*>(&WeT[jb + 1][cl * 4]);
        float4 w2 = *reinterpret_cast<float4*>(&WeT[jb + 2][cl * 4]);
        float4 w3 = *reinterpret_cast<float4*>(&WeT[jb + 3][cl * 4]);
        acc.x = fmaf(q0, w0.x, acc.x); acc.y = fmaf(q0, w0.y, acc.y); acc.z = fmaf(q0, w0.z, acc.z); acc.w = fmaf(q0, w0.w, acc.w);
        acc.x = fmaf(q1, w1.x, acc.x); acc.y = fmaf(q1, w1.y, acc.y); acc.z = fmaf(q1, w1.z, acc.z); acc.w = fmaf(q1, w1.w, acc.w);
        acc.x = fmaf(q2, w2.x, acc.x); acc.y = fmaf(q2, w2.y, acc.y); acc.z = fmaf(q2, w2.z, acc.z); acc.w = fmaf(q2, w2.w, acc.w);
        acc.x = fmaf(q3, w3.x, acc.x); acc.y = fmaf(q3, w3.y, acc.y); acc.z = fmaf(q3, w3.z, acc.z); acc.w = fmaf(q3, w3.w, acc.w);
    }
    st4(&d_T[(size_t)gw * TROW + h * 32 + cl * 4], acc);
}

// ---------------- edge attention + aggregation: one warp per destination node (round-9 proven form) ----------------
__global__ void edge_agg_kernel(int n) {
    int gw = (blockIdx.x * blockDim.x + threadIdx.x) >> 5;
    int lane = threadIdx.x & 31;
    if (gw >= n) return;
    int h = lane >> 3, cl = lane & 7;
    const float scale = 0.17677669529663687f;  // 1/sqrt(32)

    const float* kbase = d_qkv + (size_t)NN * HIDN;
    const float* vbase = d_qkv + 2ull * NN * HIDN;

    float4 qv = ld4(d_qkv + (size_t)gw * 128 + lane * 4);
    float4 Tv = ld4(d_T + (size_t)gw * TROW + h * 32 + cl * 4);
    float  Bh = d_T[(size_t)gw * TROW + 128 + h];
    float4 acc = make_float4(0.f, 0.f, 0.f, 0.f);

    int jb = d_off[gw], je = d_off[gw + 1];
    int s = (jb < je) ? d_srcPerm[jb] : 0;
    for (int j = jb; j < je; j++) {
        int s_next = (j + 1 < je) ? d_srcPerm[j + 1] : 0;   // prefetch next src idx
        float4 kv = ld4(kbase + (size_t)s * 128 + lane * 4);
        float4 ev = ld4(d_eaP + (size_t)j * 32 + cl * 4);
        float4 vv = ld4(vbase + (size_t)s * 128 + lane * 4);
        float p = qv.x * kv.x + qv.y * kv.y + qv.z * kv.z + qv.w * kv.w
                + ev.x * Tv.x + ev.y * Tv.y + ev.z * Tv.z + ev.w * Tv.w;
        p += __shfl_xor_sync(0xffffffffu, p, 1);
        p += __shfl_xor_sync(0xffffffffu, p, 2);
        p += __shfl_xor_sync(0xffffffffu, p, 4);
        float amy = (p + Bh) * scale;
        float a0 = __shfl_sync(0xffffffffu, amy, 0);
        float a1 = __shfl_sync(0xffffffffu, amy, 8);
        float a2 = __shfl_sync(0xffffffffu, amy, 16);
        float a3 = __shfl_sync(0xffffffffu, amy, 24);
        float m = fmaxf(fmaxf(a0, a1), fmaxf(a2, a3));
        float e0 = __expf(a0 - m), e1 = __expf(a1 - m), e2 = __expf(a2 - m), e3 = __expf(a3 - m);
        float w = __expf(amy - m) / (e0 + e1 + e2 + e3);
        acc.x = fmaf(w, vv.x, acc.x);
        acc.y = fmaf(w, vv.y, acc.y);
        acc.z = fmaf(w, vv.z, acc.z);
        acc.w = fmaf(w, vv.w, acc.w);
        s = s_next;
    }
    st4(d_agg + (size_t)gw * 128 + lane * 4, acc);
}

// ---------------- pooling ----------------
#define NPB 256
__global__ void pool_kernel(const float* __restrict__ h, const int* __restrict__ batch, int n) {
    int c = threadIdx.x;  // 0..127
    int b0 = blockIdx.x * NPB;
    if (b0 >= n) return;
    int b1 = min(b0 + NPB, n);
    int g = batch[b0];
    float asum = 0.f, amax = -3.402823466e38f;
    int cnt = 0;
    for (int i = b0; i < b1; i++) {
        int gn = batch[i];
        if (gn != g) {
            atomicAdd(&d_gsum[g * HIDN + c], asum);
            atomicMax(&d_gmaxk[g * HIDN + c], enc_f(amax));
            if (c == 0) atomicAdd(&d_gcnt[g], cnt);
            g = gn; asum = 0.f; amax = -3.402823466e38f; cnt = 0;
        }
        float val = h[(size_t)i * HIDN + c];
        asum += val;
        amax = fmaxf(amax, val);
        cnt++;
    }
    atomicAdd(&d_gsum[g * HIDN + c], asum);
    atomicMax(&d_gmaxk[g * HIDN + c], enc_f(amax));
    if (c == 0) atomicAdd(&d_gcnt[g], cnt);
}

// ---------------- graph head: relu([mean|max|sum] @ W1 + b1) @ W2 + b2 ----------------
__global__ void mlp_kernel(const float* __restrict__ W1, const float* __restrict__ b1,
                           const float* __restrict__ W2, const float* __restrict__ b2,
                           float* __restrict__ gout) {
    __shared__ float pooled[384];
    __shared__ float t[128];
    int g = blockIdx.x, c = threadIdx.x;
    float cnt = fmaxf((float)d_gcnt[g], 1.f);
    float sv = d_gsum[g * HIDN + c];
    pooled[c] = sv / cnt;
    pooled[128 + c] = dec_f(d_gmaxk[g * HIDN + c]);
    pooled[256 + c] = sv;
    __syncthreads();
    float acc = b1[c];
#pragma unroll 8
    for (int kk = 0; kk < 384; kk++) acc = fmaf(pooled[kk], W1[kk * 128 + c], acc);
    t[c] = fmaxf(acc, 0.f);
    __syncthreads();
    float o = b2[c];
#pragma unroll 8
    for (int kk = 0; kk < 128; kk++) o = fmaf(t[kk], W2[kk * 128 + c], o);
    gout[g * 128 + c] = o;
}

// ---------------- driver ----------------
extern "C" void kernel_launch(void* const* d_in, const int* in_sizes, int n_in,
                              void* d_out, int out_size) {
    const float* x     = (const float*)d_in[0];
    const int*   ei    = (const int*)d_in[1];
    const float* eattr = (const float*)d_in[2];
    const int*   batch = (const int*)d_in[3];
    const float* W_in  = (const float*)d_in[4];
    const float* b_in  = (const float*)d_in[5];
    const float* Wq    = (const float*)d_in[6];
    const float* bq    = (const float*)d_in[7];
    const float* Wk    = (const float*)d_in[8];
    const float* bk    = (const float*)d_in[9];
    const float* Wv    = (const float*)d_in[10];
    const float* bv    = (const float*)d_in[11];
    const float* We    = (const float*)d_in[12];
    const float* be    = (const float*)d_in[13];
    const float* Wo    = (const float*)d_in[14];
    const float* bo    = (const float*)d_in[15];
    const float* ln_g  = (const float*)d_in[16];
    const float* ln_b  = (const float*)d_in[17];
    const float* W_ep  = (const float*)d_in[18];
    const float* b_ep  = (const float*)d_in[19];
    const float* W1    = (const float*)d_in[20];
    const float* b1    = (const float*)d_in[21];
    const float* W2    = (const float*)d_in[22];
    const float* b2    = (const float*)d_in[23];

    int N = in_sizes[0] / 128;
    int E = in_sizes[1] / 2;

    float* out  = (float*)d_out;
    float* h    = out;                       // [N,128] lives directly in d_out
    float* gout = out + (size_t)N * HIDN;    // [G,128]

    void *pqkv, *pagg;
    cudaGetSymbolAddress(&pqkv, d_qkv);
    cudaGetSymbolAddress(&pagg, d_agg);

    const int* src = ei;
    const int* dst = ei + E;

    int gE = (E + 255) / 256;
    int gN = (N + 255) / 256;
    int gW = (N + 7) / 8;         // warp-per-node kernels, 256-thread blocks
    int gEW = (E + 7) / 8;        // warp-per-edge
    int gGemm = (N + 127) / 128;

    // CSR build + edge projection (layer-independent); zero_csr also does pool init
    zero_csr_kernel<<<gN, 256>>>(N);
    hist_kernel<<<gE, 256>>>(dst, E);
    scan_kernel<<<1, 1024>>>(N);
    scatter_kernel<<<gE, 256>>>(src, dst, E);
    ea_proj_kernel<<<gEW, 256>>>(eattr, W_ep, b_ep, E);

    // input projection: h = x @ W_in + b_in
    gemm128_tf32_kernel<<<gGemm, 256>>>(x, W_in, b_in, h, N);

    for (int l = 0; l < 3; l++) {
        const float* Wq_l = Wq + (size_t)l * 128 * 128;
        const float* Wk_l = Wk + (size_t)l * 128 * 128;
        const float* Wv_l = Wv + (size_t)l * 128 * 128;
        const float* Wo_l = Wo + (size_t)l * 128 * 128;
        const float* We_l = We + (size_t)l * 32 * 128;

        pack_qkv_kernel<<<64, 256>>>(Wq_l, Wk_l, Wv_l,
                                     bq + l * 128, bk + l * 128, bv + l * 128);
        qkv_gemm_tf32_kernel<<<3 * gGemm, 256>>>(h, gGemm, N);
        t_kernel<<<gW, 256>>>((const float*)pqkv, We_l, be + l * 128, N);
        edge_agg_kernel<<<gW, 256>>>(N);
        gemm_ln_tf32_kernel<<<gGemm, 256>>>((const float*)pagg, Wo_l, bo + l * 128,
                                            ln_g + l * 128, ln_b + l * 128, h, N);
    }

    pool_kernel<<<(N + NPB - 1) / NPB, 128>>>(h, batch, N);
    mlp_kernel<<<GG, 128>>>(W1, b1, W2, b2, gout);
}